// round 2
// baseline (speedup 1.0000x reference)
#include <cuda_runtime.h>
#include <cuda_bf16.h>
#include <cstdint>

// Problem constants
#define BB   2
#define TT   2048
#define CC   1024
#define HH   16
#define DD   64
#define MROWS (BB*TT)          // 4096
#define SCALE 0.125f           // 1/sqrt(64)

// Scratch (device globals — no allocations allowed)
__device__ float g_q[BB*HH*TT*DD];   // [B*H, T, D]
__device__ float g_k[BB*HH*TT*DD];
__device__ float g_v[BB*HH*TT*DD];
__device__ float g_y[BB*TT*CC];      // [B, T, C] attention output

// ---------------------------------------------------------------------------
// Kernel 1: qkv = x @ w_qkv, scattered into q/k/v [B*H, T, D]
// M=4096, K=1024, N=3072. Tile 128x128x16, 256 threads, 8x8 per thread.
// ---------------------------------------------------------------------------
__global__ __launch_bounds__(256) void qkv_gemm_kernel(
    const float* __restrict__ x, const float* __restrict__ w)
{
    __shared__ float As[16][128];
    __shared__ float Bs[16][128];

    const int bx = blockIdx.x;   // N tile (0..23)
    const int by = blockIdx.y;   // M tile (0..31)
    const int tid = threadIdx.x;
    const int tx = tid & 15;
    const int ty = tid >> 4;

    float acc[8][8];
    #pragma unroll
    for (int i = 0; i < 8; i++)
        #pragma unroll
        for (int j = 0; j < 8; j++) acc[i][j] = 0.f;

    const float* Ab = x + (size_t)(by * 128) * CC;
    const float* Bb = w + bx * 128;

    for (int k0 = 0; k0 < CC; k0 += 16) {
        // A tile: 128 rows x 16 cols -> store transposed As[k][m]
        #pragma unroll
        for (int u = 0; u < 2; u++) {
            int f = u * 256 + tid;          // 0..511
            int row = f >> 2, cv = f & 3;   // 4 float4 per row
            float4 a4 = *(const float4*)(Ab + (size_t)row * CC + k0 + cv * 4);
            As[cv*4+0][row] = a4.x; As[cv*4+1][row] = a4.y;
            As[cv*4+2][row] = a4.z; As[cv*4+3][row] = a4.w;
        }
        // B tile: 16 rows x 128 cols
        #pragma unroll
        for (int u = 0; u < 2; u++) {
            int f = u * 256 + tid;
            int row = f >> 5, cv = f & 31;  // 32 float4 per row
            float4 b4 = *(const float4*)(Bb + (size_t)(k0 + row) * (3*CC) + cv * 4);
            *(float4*)&Bs[row][cv*4] = b4;
        }
        __syncthreads();
        #pragma unroll
        for (int k = 0; k < 16; k++) {
            float a[8], b[8];
            #pragma unroll
            for (int i = 0; i < 8; i++) a[i] = As[k][ty*8+i];
            #pragma unroll
            for (int j = 0; j < 8; j++) b[j] = Bs[k][tx*8+j];
            #pragma unroll
            for (int i = 0; i < 8; i++)
                #pragma unroll
                for (int j = 0; j < 8; j++) acc[i][j] += a[i]*b[j];
        }
        __syncthreads();
    }

    // Scatter epilogue: n = g*1024 + h*64 + d ; dest[(b*16+h)*T + t][d]
    #pragma unroll
    for (int i = 0; i < 8; i++) {
        int m = by*128 + ty*8 + i;
        int b = m >> 11, t = m & (TT-1);
        #pragma unroll
        for (int j = 0; j < 8; j++) {
            int n = bx*128 + tx*8 + j;
            int g = n >> 10;
            int rem = n & 1023;
            int h = rem >> 6, d = rem & 63;
            float* dst = (g == 0) ? g_q : (g == 1) ? g_k : g_v;
            dst[(((size_t)(b*HH + h))*TT + t)*DD + d] = acc[i][j];
        }
    }
}

// ---------------------------------------------------------------------------
// Kernel 2: flash attention, fp32. One block = 64 query rows of one (b,h).
// 256 threads, 16x16 layout, 4x4 register tiles for both 64x64x64 GEMMs.
// ---------------------------------------------------------------------------
#define QP 65   // pad for Q/K/S smem rows
#define FA_SMEM_BYTES ((64*QP /*Q*/ + 64*QP /*K*/ + 64*64 /*V*/ + 64*QP /*S*/ + 3*64) * 4)

__global__ __launch_bounds__(256) void flash_attn_kernel()
{
    extern __shared__ float sm[];
    float* Qs = sm;                 // [64][65]
    float* Ks = Qs + 64*QP;         // [64][65]
    float* Vs = Ks + 64*QP;         // [64][64]
    float* Ss = Vs + 64*64;         // [64][65]
    float* mrow = Ss + 64*QP;       // [64]
    float* lrow = mrow + 64;        // [64]
    float* arow = lrow + 64;        // [64]

    const int qi = blockIdx.x;      // query tile (0..31)
    const int bh = blockIdx.y;      // b*16+h (0..31)
    const int b = bh >> 4, h = bh & 15;
    const int tid = threadIdx.x;
    const int tx = tid & 15;
    const int ty = tid >> 4;

    // Load Q tile [64][64] (scalar stores because of pad)
    const float* qptr = g_q + ((size_t)bh * TT + qi*64) * DD;
    for (int f = tid; f < 1024; f += 256) {       // 1024 float4
        int row = f >> 4, c = (f & 15) * 4;
        float4 v = ((const float4*)qptr)[f];
        Qs[row*QP + c+0] = v.x; Qs[row*QP + c+1] = v.y;
        Qs[row*QP + c+2] = v.z; Qs[row*QP + c+3] = v.w;
    }
    if (tid < 64) { mrow[tid] = -1e30f; lrow[tid] = 0.f; }

    float acc[4][4];
    #pragma unroll
    for (int i = 0; i < 4; i++)
        #pragma unroll
        for (int j = 0; j < 4; j++) acc[i][j] = 0.f;

    __syncthreads();

    const int nkt = qi + 1;   // causal: only key tiles <= query tile
    for (int kt = 0; kt < nkt; kt++) {
        // Load K, V tiles
        const float* kptr = g_k + ((size_t)bh * TT + kt*64) * DD;
        const float* vptr = g_v + ((size_t)bh * TT + kt*64) * DD;
        for (int f = tid; f < 1024; f += 256) {
            int row = f >> 4, c = (f & 15) * 4;
            float4 kv = ((const float4*)kptr)[f];
            Ks[row*QP + c+0] = kv.x; Ks[row*QP + c+1] = kv.y;
            Ks[row*QP + c+2] = kv.z; Ks[row*QP + c+3] = kv.w;
            float4 vv = ((const float4*)vptr)[f];
            *(float4*)&Vs[row*64 + c] = vv;
        }
        __syncthreads();

        // S = Q @ K^T  (64x64x64), 4x4 per thread
        float s[4][4];
        #pragma unroll
        for (int i = 0; i < 4; i++)
            #pragma unroll
            for (int j = 0; j < 4; j++) s[i][j] = 0.f;
        for (int d = 0; d < 64; d++) {
            float a[4], kb[4];
            #pragma unroll
            for (int i = 0; i < 4; i++) a[i] = Qs[(ty*4+i)*QP + d];
            #pragma unroll
            for (int j = 0; j < 4; j++) kb[j] = Ks[(tx*4+j)*QP + d];
            #pragma unroll
            for (int i = 0; i < 4; i++)
                #pragma unroll
                for (int j = 0; j < 4; j++) s[i][j] += a[i]*kb[j];
        }
        // Scale + causal mask, write to Ss
        const int qbase = qi*64, kbase = kt*64;
        #pragma unroll
        for (int i = 0; i < 4; i++) {
            int qr = qbase + ty*4 + i;
            #pragma unroll
            for (int j = 0; j < 4; j++) {
                int kc = kbase + tx*4 + j;
                float val = s[i][j] * SCALE;
                if (kc > qr) val = -1e30f;
                Ss[(ty*4+i)*QP + tx*4+j] = val;
            }
        }
        __syncthreads();

        // Online softmax per row (threads 0..63)
        if (tid < 64) {
            float* srow = Ss + tid*QP;
            float mo = mrow[tid];
            float mn = mo;
            #pragma unroll 8
            for (int c = 0; c < 64; c++) mn = fmaxf(mn, srow[c]);
            float al = __expf(mo - mn);
            float sum = 0.f;
            #pragma unroll 8
            for (int c = 0; c < 64; c++) {
                float p = __expf(srow[c] - mn);
                srow[c] = p;
                sum += p;
            }
            lrow[tid] = lrow[tid]*al + sum;
            mrow[tid] = mn;
            arow[tid] = al;
        }
        __syncthreads();

        // Rescale accumulators, then O += P @ V
        float al[4];
        #pragma unroll
        for (int i = 0; i < 4; i++) al[i] = arow[ty*4+i];
        #pragma unroll
        for (int i = 0; i < 4; i++)
            #pragma unroll
            for (int j = 0; j < 4; j++) acc[i][j] *= al[i];

        for (int kk = 0; kk < 64; kk++) {
            float p[4], vb[4];
            #pragma unroll
            for (int i = 0; i < 4; i++) p[i] = Ss[(ty*4+i)*QP + kk];
            #pragma unroll
            for (int j = 0; j < 4; j++) vb[j] = Vs[kk*64 + tx*4+j];
            #pragma unroll
            for (int i = 0; i < 4; i++)
                #pragma unroll
                for (int j = 0; j < 4; j++) acc[i][j] += p[i]*vb[j];
        }
        __syncthreads();   // before K/V/S reuse next iteration
    }

    // Epilogue: y[b, t, h*64+d] = acc / l
    float inv[4];
    #pragma unroll
    for (int i = 0; i < 4; i++) inv[i] = 1.f / lrow[ty*4+i];
    #pragma unroll
    for (int i = 0; i < 4; i++) {
        int t = qi*64 + ty*4 + i;
        float* yrow = g_y + ((size_t)b*TT + t)*CC + h*DD;
        #pragma unroll
        for (int j = 0; j < 4; j++)
            yrow[tx*4+j] = acc[i][j] * inv[i];
    }
}

// ---------------------------------------------------------------------------
// Kernel 3: out = y @ w_proj + b_proj. M=4096, K=1024, N=1024.
// ---------------------------------------------------------------------------
__global__ __launch_bounds__(256) void proj_gemm_kernel(
    const float* __restrict__ w, const float* __restrict__ bias,
    float* __restrict__ out)
{
    __shared__ float As[16][128];
    __shared__ float Bs[16][128];

    const int bx = blockIdx.x;   // N tile (0..7)
    const int by = blockIdx.y;   // M tile (0..31)
    const int tid = threadIdx.x;
    const int tx = tid & 15;
    const int ty = tid >> 4;

    float acc[8][8];
    #pragma unroll
    for (int i = 0; i < 8; i++)
        #pragma unroll
        for (int j = 0; j < 8; j++) acc[i][j] = 0.f;

    const float* Ab = g_y + (size_t)(by * 128) * CC;
    const float* Bb = w + bx * 128;

    for (int k0 = 0; k0 < CC; k0 += 16) {
        #pragma unroll
        for (int u = 0; u < 2; u++) {
            int f = u * 256 + tid;
            int row = f >> 2, cv = f & 3;
            float4 a4 = *(const float4*)(Ab + (size_t)row * CC + k0 + cv * 4);
            As[cv*4+0][row] = a4.x; As[cv*4+1][row] = a4.y;
            As[cv*4+2][row] = a4.z; As[cv*4+3][row] = a4.w;
        }
        #pragma unroll
        for (int u = 0; u < 2; u++) {
            int f = u * 256 + tid;
            int row = f >> 5, cv = f & 31;
            float4 b4 = *(const float4*)(Bb + (size_t)(k0 + row) * CC + cv * 4);
            *(float4*)&Bs[row][cv*4] = b4;
        }
        __syncthreads();
        #pragma unroll
        for (int k = 0; k < 16; k++) {
            float a[8], b[8];
            #pragma unroll
            for (int i = 0; i < 8; i++) a[i] = As[k][ty*8+i];
            #pragma unroll
            for (int j = 0; j < 8; j++) b[j] = Bs[k][tx*8+j];
            #pragma unroll
            for (int i = 0; i < 8; i++)
                #pragma unroll
                for (int j = 0; j < 8; j++) acc[i][j] += a[i]*b[j];
        }
        __syncthreads();
    }

    #pragma unroll
    for (int i = 0; i < 8; i++) {
        int m = by*128 + ty*8 + i;
        #pragma unroll
        for (int j = 0; j < 8; j++) {
            int n = bx*128 + tx*8 + j;
            out[(size_t)m * CC + n] = acc[i][j] + bias[n];
        }
    }
}

// ---------------------------------------------------------------------------
extern "C" void kernel_launch(void* const* d_in, const int* in_sizes, int n_in,
                              void* d_out, int out_size)
{
    const float* x      = (const float*)d_in[0];   // [B,T,C]
    const float* w_qkv  = (const float*)d_in[1];   // [C,3C]
    const float* w_proj = (const float*)d_in[2];   // [C,C]
    const float* b_proj = (const float*)d_in[3];   // [C]
    float* out = (float*)d_out;                    // [B,T,C]

    static bool attr_set = false;
    if (!attr_set) {
        cudaFuncSetAttribute(flash_attn_kernel,
                             cudaFuncAttributeMaxDynamicSharedMemorySize,
                             FA_SMEM_BYTES);
        attr_set = true;
    }

    // 1) QKV projection + scatter
    {
        dim3 grid(3*CC/128, MROWS/128);   // (24, 32)
        qkv_gemm_kernel<<<grid, 256>>>(x, w_qkv);
    }
    // 2) Flash attention
    {
        dim3 grid(TT/64, BB*HH);          // (32, 32)
        flash_attn_kernel<<<grid, 256, FA_SMEM_BYTES>>>();
    }
    // 3) Output projection + bias
    {
        dim3 grid(CC/128, MROWS/128);     // (8, 32)
        proj_gemm_kernel<<<grid, 256>>>(w_proj, b_proj, out);
    }
}

// round 5
// speedup vs baseline: 1.7277x; 1.7277x over previous
#include <cuda_runtime.h>
#include <cuda_bf16.h>
#include <cstdint>

// Problem constants
#define BB   2
#define TT   2048
#define CC   1024
#define HH   16
#define DD   64
#define MROWS (BB*TT)          // 4096
#define SCALE 0.125f           // 1/sqrt(64)

// Scratch (device globals — no allocations allowed)
__device__ float g_q[BB*HH*TT*DD];   // [B*H, T, D]
__device__ float g_k[BB*HH*TT*DD];
__device__ float g_v[BB*HH*TT*DD];
__device__ float g_y[BB*TT*CC];      // [B, T, C] attention output

// ===========================================================================
// tf32 mma.sync helpers (sm_80+ path — compiles for plain sm_103)
// ===========================================================================
__device__ __forceinline__ uint32_t f2tf32(float x) {
    uint32_t y;
    asm("cvt.rna.tf32.f32 %0, %1;" : "=r"(y) : "f"(x));
    return y;
}

__device__ __forceinline__ void mma_tf32_16x8x8(float* c, const uint32_t* a,
                                                const uint32_t* b) {
    asm volatile(
        "mma.sync.aligned.m16n8k8.row.col.f32.tf32.tf32.f32 "
        "{%0,%1,%2,%3}, {%4,%5,%6,%7}, {%8,%9}, {%0,%1,%2,%3};\n"
        : "+f"(c[0]), "+f"(c[1]), "+f"(c[2]), "+f"(c[3])
        : "r"(a[0]), "r"(a[1]), "r"(a[2]), "r"(a[3]),
          "r"(b[0]), "r"(b[1]));
}

// Smem pitches chosen so fragment loads are bank-conflict-free:
//   A: addr = 36*m + k  ->  (4m + k) mod 32, m=lane>>2 in 0..7, k=lane&3  : distinct
//   B: addr = 132*k + n ->  (4k + n) mod 32, k=lane&3, n=lane>>2 in 0..7  : distinct
#define AP 36
#define BPITCH 132

struct GemmSmem {
    uint32_t As[128 * AP];      // [m][k] tf32 bits, 128 x 32 (pitch 36)
    uint32_t Bs[32 * BPITCH];   // [k][n] tf32 bits, 32 x 128 (pitch 132)
};

// Mainloop: acc[2][8][4] = A[128 x 1024] @ B tile (128 cols of B)
// A row-major lda, B row-major ldb. 256 threads.
__device__ __forceinline__ void gemm_tf32_mainloop(
    GemmSmem* sm, const float* __restrict__ A, int lda,
    const float* __restrict__ B, int ldb, float acc[2][8][4])
{
    const int tid = threadIdx.x;
    const int wid = tid >> 5;
    const int lane = tid & 31;
    const int warp_m = wid & 3;          // 4 warps along M (32 rows each)
    const int warp_n = wid >> 2;         // 2 warps along N (64 cols each)
    const int g = lane >> 2;             // group id 0..7
    const int t = lane & 3;              // thread-in-group 0..3

    #pragma unroll
    for (int mi = 0; mi < 2; mi++)
        #pragma unroll
        for (int ni = 0; ni < 8; ni++)
            #pragma unroll
            for (int r = 0; r < 4; r++) acc[mi][ni][r] = 0.f;

    for (int c = 0; c < CC / 32; c++) {
        // A chunk: 128 rows x 32 floats (1024 float4, 4 per thread)
        #pragma unroll
        for (int u = 0; u < 4; u++) {
            int f = u * 256 + tid;
            int row = f >> 3, cv = f & 7;
            float4 a4 = *(const float4*)(A + (size_t)row * lda + c * 32 + cv * 4);
            uint32_t* p = &sm->As[row * AP + cv * 4];
            p[0] = f2tf32(a4.x); p[1] = f2tf32(a4.y);
            p[2] = f2tf32(a4.z); p[3] = f2tf32(a4.w);
        }
        // B chunk: 32 k-rows x 128 cols
        #pragma unroll
        for (int u = 0; u < 4; u++) {
            int f = u * 256 + tid;
            int row = f >> 5, cv = f & 31;
            float4 b4 = *(const float4*)(B + (size_t)(c * 32 + row) * ldb + cv * 4);
            uint32_t* p = &sm->Bs[row * BPITCH + cv * 4];
            p[0] = f2tf32(b4.x); p[1] = f2tf32(b4.y);
            p[2] = f2tf32(b4.z); p[3] = f2tf32(b4.w);
        }
        __syncthreads();

        #pragma unroll
        for (int ks = 0; ks < 4; ks++) {
            const int k0 = ks * 8;
            uint32_t af[2][4];
            #pragma unroll
            for (int mi = 0; mi < 2; mi++) {
                int mb = warp_m * 32 + mi * 16;
                af[mi][0] = sm->As[(mb + g) * AP + k0 + t];
                af[mi][1] = sm->As[(mb + g + 8) * AP + k0 + t];
                af[mi][2] = sm->As[(mb + g) * AP + k0 + t + 4];
                af[mi][3] = sm->As[(mb + g + 8) * AP + k0 + t + 4];
            }
            uint32_t bf[8][2];
            #pragma unroll
            for (int ni = 0; ni < 8; ni++) {
                int nb = warp_n * 64 + ni * 8;
                bf[ni][0] = sm->Bs[(k0 + t) * BPITCH + nb + g];
                bf[ni][1] = sm->Bs[(k0 + t + 4) * BPITCH + nb + g];
            }
            #pragma unroll
            for (int mi = 0; mi < 2; mi++)
                #pragma unroll
                for (int ni = 0; ni < 8; ni++)
                    mma_tf32_16x8x8(acc[mi][ni], af[mi], bf[ni]);
        }
        __syncthreads();
    }
}

// ---------------------------------------------------------------------------
// Kernel 1: QKV projection + scatter to g_q/g_k/g_v
// grid (24, 32), block 256
// ---------------------------------------------------------------------------
__global__ __launch_bounds__(256, 2) void qkv_mma_kernel(
    const float* __restrict__ x, const float* __restrict__ w)
{
    __shared__ GemmSmem sm;
    const int bx = blockIdx.x;   // N tile of 3072 (0..23)
    const int by = blockIdx.y;   // M tile (0..31)
    const int tid = threadIdx.x;
    const int wid = tid >> 5, lane = tid & 31;
    const int warp_m = wid & 3, warp_n = wid >> 2;
    const int g = lane >> 2, t = lane & 3;

    float acc[2][8][4];
    gemm_tf32_mainloop(&sm, x + (size_t)(by * 128) * CC, CC,
                       w + bx * 128, 3 * CC, acc);

    // Tile lies entirely within q, k, or v (bx*128 aligned within 1024-blocks)
    const int g3 = bx >> 3;
    float* dstbase = (g3 == 0) ? g_q : (g3 == 1) ? g_k : g_v;

    #pragma unroll
    for (int mi = 0; mi < 2; mi++) {
        #pragma unroll
        for (int rr = 0; rr < 2; rr++) {         // c0/c1 vs c2/c3 (row, row+8)
            int m = by * 128 + warp_m * 32 + mi * 16 + g + rr * 8;
            int b = m >> 11, tloc = m & (TT - 1);
            #pragma unroll
            for (int ni = 0; ni < 8; ni++) {
                int n = bx * 128 + warp_n * 64 + ni * 8 + 2 * t;
                int rem = n & 1023;
                int h = rem >> 6, d = rem & 63;  // d even
                float2 v2 = make_float2(acc[mi][ni][rr * 2], acc[mi][ni][rr * 2 + 1]);
                *(float2*)&dstbase[(((size_t)(b * HH + h)) * TT + tloc) * DD + d] = v2;
            }
        }
    }
}

// ---------------------------------------------------------------------------
// Kernel 3: out = y @ w_proj + b_proj
// grid (8, 32), block 256
// ---------------------------------------------------------------------------
__global__ __launch_bounds__(256, 2) void proj_mma_kernel(
    const float* __restrict__ w, const float* __restrict__ bias,
    float* __restrict__ out)
{
    __shared__ GemmSmem sm;
    const int bx = blockIdx.x;   // N tile (0..7)
    const int by = blockIdx.y;   // M tile (0..31)
    const int tid = threadIdx.x;
    const int wid = tid >> 5, lane = tid & 31;
    const int warp_m = wid & 3, warp_n = wid >> 2;
    const int g = lane >> 2, t = lane & 3;

    float acc[2][8][4];
    gemm_tf32_mainloop(&sm, g_y + (size_t)(by * 128) * CC, CC,
                       w + bx * 128, CC, acc);

    #pragma unroll
    for (int mi = 0; mi < 2; mi++) {
        #pragma unroll
        for (int rr = 0; rr < 2; rr++) {
            int m = by * 128 + warp_m * 32 + mi * 16 + g + rr * 8;
            #pragma unroll
            for (int ni = 0; ni < 8; ni++) {
                int n = bx * 128 + warp_n * 64 + ni * 8 + 2 * t;
                float2 v2;
                v2.x = acc[mi][ni][rr * 2]     + bias[n];
                v2.y = acc[mi][ni][rr * 2 + 1] + bias[n + 1];
                *(float2*)&out[(size_t)m * CC + n] = v2;
            }
        }
    }
}

// ---------------------------------------------------------------------------
// Kernel 2: flash attention, fp32 SIMT (unchanged from R2 passing version)
// ---------------------------------------------------------------------------
#define QP 65
#define FA_SMEM_BYTES ((64*QP + 64*QP + 64*64 + 64*QP + 3*64) * 4)

__global__ __launch_bounds__(256) void flash_attn_kernel()
{
    extern __shared__ float smf[];
    float* Qs = smf;
    float* Ks = Qs + 64*QP;
    float* Vs = Ks + 64*QP;
    float* Ss = Vs + 64*64;
    float* mrow = Ss + 64*QP;
    float* lrow = mrow + 64;
    float* arow = lrow + 64;

    const int qi = blockIdx.x;
    const int bh = blockIdx.y;
    const int b = bh >> 4, h = bh & 15;
    const int tid = threadIdx.x;
    const int tx = tid & 15;
    const int ty = tid >> 4;

    const float* qptr = g_q + ((size_t)bh * TT + qi*64) * DD;
    for (int f = tid; f < 1024; f += 256) {
        int row = f >> 4, c = (f & 15) * 4;
        float4 v = ((const float4*)qptr)[f];
        Qs[row*QP + c+0] = v.x; Qs[row*QP + c+1] = v.y;
        Qs[row*QP + c+2] = v.z; Qs[row*QP + c+3] = v.w;
    }
    if (tid < 64) { mrow[tid] = -1e30f; lrow[tid] = 0.f; }

    float acc[4][4];
    #pragma unroll
    for (int i = 0; i < 4; i++)
        #pragma unroll
        for (int j = 0; j < 4; j++) acc[i][j] = 0.f;

    __syncthreads();

    const int nkt = qi + 1;
    for (int kt = 0; kt < nkt; kt++) {
        const float* kptr = g_k + ((size_t)bh * TT + kt*64) * DD;
        const float* vptr = g_v + ((size_t)bh * TT + kt*64) * DD;
        for (int f = tid; f < 1024; f += 256) {
            int row = f >> 4, c = (f & 15) * 4;
            float4 kv = ((const float4*)kptr)[f];
            Ks[row*QP + c+0] = kv.x; Ks[row*QP + c+1] = kv.y;
            Ks[row*QP + c+2] = kv.z; Ks[row*QP + c+3] = kv.w;
            float4 vv = ((const float4*)vptr)[f];
            *(float4*)&Vs[row*64 + c] = vv;
        }
        __syncthreads();

        float s[4][4];
        #pragma unroll
        for (int i = 0; i < 4; i++)
            #pragma unroll
            for (int j = 0; j < 4; j++) s[i][j] = 0.f;
        for (int d = 0; d < 64; d++) {
            float a[4], kb[4];
            #pragma unroll
            for (int i = 0; i < 4; i++) a[i] = Qs[(ty*4+i)*QP + d];
            #pragma unroll
            for (int j = 0; j < 4; j++) kb[j] = Ks[(tx*4+j)*QP + d];
            #pragma unroll
            for (int i = 0; i < 4; i++)
                #pragma unroll
                for (int j = 0; j < 4; j++) s[i][j] += a[i]*kb[j];
        }
        const int qbase = qi*64, kbase = kt*64;
        #pragma unroll
        for (int i = 0; i < 4; i++) {
            int qr = qbase + ty*4 + i;
            #pragma unroll
            for (int j = 0; j < 4; j++) {
                int kc = kbase + tx*4 + j;
                float val = s[i][j] * SCALE;
                if (kc > qr) val = -1e30f;
                Ss[(ty*4+i)*QP + tx*4+j] = val;
            }
        }
        __syncthreads();

        if (tid < 64) {
            float* srow = Ss + tid*QP;
            float mo = mrow[tid];
            float mn = mo;
            #pragma unroll 8
            for (int c = 0; c < 64; c++) mn = fmaxf(mn, srow[c]);
            float al = __expf(mo - mn);
            float sum = 0.f;
            #pragma unroll 8
            for (int c = 0; c < 64; c++) {
                float p = __expf(srow[c] - mn);
                srow[c] = p;
                sum += p;
            }
            lrow[tid] = lrow[tid]*al + sum;
            mrow[tid] = mn;
            arow[tid] = al;
        }
        __syncthreads();

        float al[4];
        #pragma unroll
        for (int i = 0; i < 4; i++) al[i] = arow[ty*4+i];
        #pragma unroll
        for (int i = 0; i < 4; i++)
            #pragma unroll
            for (int j = 0; j < 4; j++) acc[i][j] *= al[i];

        for (int kk = 0; kk < 64; kk++) {
            float p[4], vb[4];
            #pragma unroll
            for (int i = 0; i < 4; i++) p[i] = Ss[(ty*4+i)*QP + kk];
            #pragma unroll
            for (int j = 0; j < 4; j++) vb[j] = Vs[kk*64 + tx*4+j];
            #pragma unroll
            for (int i = 0; i < 4; i++)
                #pragma unroll
                for (int j = 0; j < 4; j++) acc[i][j] += p[i]*vb[j];
        }
        __syncthreads();
    }

    float inv[4];
    #pragma unroll
    for (int i = 0; i < 4; i++) inv[i] = 1.f / lrow[ty*4+i];
    #pragma unroll
    for (int i = 0; i < 4; i++) {
        int t = qi*64 + ty*4 + i;
        float* yrow = g_y + ((size_t)b*TT + t)*CC + h*DD;
        #pragma unroll
        for (int j = 0; j < 4; j++)
            yrow[tx*4+j] = acc[i][j] * inv[i];
    }
}

// ---------------------------------------------------------------------------
extern "C" void kernel_launch(void* const* d_in, const int* in_sizes, int n_in,
                              void* d_out, int out_size)
{
    const float* x      = (const float*)d_in[0];
    const float* w_qkv  = (const float*)d_in[1];
    const float* w_proj = (const float*)d_in[2];
    const float* b_proj = (const float*)d_in[3];
    float* out = (float*)d_out;

    static bool attr_set = false;
    if (!attr_set) {
        cudaFuncSetAttribute(flash_attn_kernel,
                             cudaFuncAttributeMaxDynamicSharedMemorySize,
                             FA_SMEM_BYTES);
        attr_set = true;
    }

    {
        dim3 grid(3*CC/128, MROWS/128);   // (24, 32)
        qkv_mma_kernel<<<grid, 256>>>(x, w_qkv);
    }
    {
        dim3 grid(TT/64, BB*HH);          // (32, 32)
        flash_attn_kernel<<<grid, 256, FA_SMEM_BYTES>>>();
    }
    {
        dim3 grid(CC/128, MROWS/128);     // (8, 32)
        proj_mma_kernel<<<grid, 256>>>(w_proj, b_proj, out);
    }
}

// round 6
// speedup vs baseline: 2.9023x; 1.6798x over previous
#include <cuda_runtime.h>
#include <cuda_bf16.h>
#include <cstdint>

// Problem constants
#define BB   2
#define TT   2048
#define CC   1024
#define HH   16
#define DD   64
#define MROWS (BB*TT)          // 4096
#define SCALE 0.125f           // 1/sqrt(64)

// Scratch (device globals — no allocations allowed)
__device__ float g_q[BB*HH*TT*DD];   // [B*H, T, D]
__device__ float g_k[BB*HH*TT*DD];
__device__ float g_v[BB*HH*TT*DD];
__device__ float g_y[BB*TT*CC];      // [B, T, C] attention output

// ===========================================================================
// tf32 mma.sync helpers (sm_80+ path — compiles for plain sm_103)
// ===========================================================================
__device__ __forceinline__ uint32_t f2tf32(float x) {
    uint32_t y;
    asm("cvt.rna.tf32.f32 %0, %1;" : "=r"(y) : "f"(x));
    return y;
}

__device__ __forceinline__ void mma_tf32_16x8x8(float* c, const uint32_t* a,
                                                const uint32_t* b) {
    asm volatile(
        "mma.sync.aligned.m16n8k8.row.col.f32.tf32.tf32.f32 "
        "{%0,%1,%2,%3}, {%4,%5,%6,%7}, {%8,%9}, {%0,%1,%2,%3};\n"
        : "+f"(c[0]), "+f"(c[1]), "+f"(c[2]), "+f"(c[3])
        : "r"(a[0]), "r"(a[1]), "r"(a[2]), "r"(a[3]),
          "r"(b[0]), "r"(b[1]));
}

// ===========================================================================
// GEMM kernels (unchanged from R5 passing version)
// ===========================================================================
#define AP 36
#define BPITCH 132

struct GemmSmem {
    uint32_t As[128 * AP];      // [m][k] tf32 bits, 128 x 32 (pitch 36)
    uint32_t Bs[32 * BPITCH];   // [k][n] tf32 bits, 32 x 128 (pitch 132)
};

__device__ __forceinline__ void gemm_tf32_mainloop(
    GemmSmem* sm, const float* __restrict__ A, int lda,
    const float* __restrict__ B, int ldb, float acc[2][8][4])
{
    const int tid = threadIdx.x;
    const int wid = tid >> 5;
    const int lane = tid & 31;
    const int warp_m = wid & 3;
    const int warp_n = wid >> 2;
    const int g = lane >> 2;
    const int t = lane & 3;

    #pragma unroll
    for (int mi = 0; mi < 2; mi++)
        #pragma unroll
        for (int ni = 0; ni < 8; ni++)
            #pragma unroll
            for (int r = 0; r < 4; r++) acc[mi][ni][r] = 0.f;

    for (int c = 0; c < CC / 32; c++) {
        #pragma unroll
        for (int u = 0; u < 4; u++) {
            int f = u * 256 + tid;
            int row = f >> 3, cv = f & 7;
            float4 a4 = *(const float4*)(A + (size_t)row * lda + c * 32 + cv * 4);
            uint32_t* p = &sm->As[row * AP + cv * 4];
            p[0] = f2tf32(a4.x); p[1] = f2tf32(a4.y);
            p[2] = f2tf32(a4.z); p[3] = f2tf32(a4.w);
        }
        #pragma unroll
        for (int u = 0; u < 4; u++) {
            int f = u * 256 + tid;
            int row = f >> 5, cv = f & 31;
            float4 b4 = *(const float4*)(B + (size_t)(c * 32 + row) * ldb + cv * 4);
            uint32_t* p = &sm->Bs[row * BPITCH + cv * 4];
            p[0] = f2tf32(b4.x); p[1] = f2tf32(b4.y);
            p[2] = f2tf32(b4.z); p[3] = f2tf32(b4.w);
        }
        __syncthreads();

        #pragma unroll
        for (int ks = 0; ks < 4; ks++) {
            const int k0 = ks * 8;
            uint32_t af[2][4];
            #pragma unroll
            for (int mi = 0; mi < 2; mi++) {
                int mb = warp_m * 32 + mi * 16;
                af[mi][0] = sm->As[(mb + g) * AP + k0 + t];
                af[mi][1] = sm->As[(mb + g + 8) * AP + k0 + t];
                af[mi][2] = sm->As[(mb + g) * AP + k0 + t + 4];
                af[mi][3] = sm->As[(mb + g + 8) * AP + k0 + t + 4];
            }
            uint32_t bf[8][2];
            #pragma unroll
            for (int ni = 0; ni < 8; ni++) {
                int nb = warp_n * 64 + ni * 8;
                bf[ni][0] = sm->Bs[(k0 + t) * BPITCH + nb + g];
                bf[ni][1] = sm->Bs[(k0 + t + 4) * BPITCH + nb + g];
            }
            #pragma unroll
            for (int mi = 0; mi < 2; mi++)
                #pragma unroll
                for (int ni = 0; ni < 8; ni++)
                    mma_tf32_16x8x8(acc[mi][ni], af[mi], bf[ni]);
        }
        __syncthreads();
    }
}

__global__ __launch_bounds__(256, 2) void qkv_mma_kernel(
    const float* __restrict__ x, const float* __restrict__ w)
{
    __shared__ GemmSmem sm;
    const int bx = blockIdx.x;
    const int by = blockIdx.y;
    const int tid = threadIdx.x;
    const int wid = tid >> 5, lane = tid & 31;
    const int warp_m = wid & 3, warp_n = wid >> 2;
    const int g = lane >> 2, t = lane & 3;

    float acc[2][8][4];
    gemm_tf32_mainloop(&sm, x + (size_t)(by * 128) * CC, CC,
                       w + bx * 128, 3 * CC, acc);

    const int g3 = bx >> 3;
    float* dstbase = (g3 == 0) ? g_q : (g3 == 1) ? g_k : g_v;

    #pragma unroll
    for (int mi = 0; mi < 2; mi++) {
        #pragma unroll
        for (int rr = 0; rr < 2; rr++) {
            int m = by * 128 + warp_m * 32 + mi * 16 + g + rr * 8;
            int b = m >> 11, tloc = m & (TT - 1);
            #pragma unroll
            for (int ni = 0; ni < 8; ni++) {
                int n = bx * 128 + warp_n * 64 + ni * 8 + 2 * t;
                int rem = n & 1023;
                int h = rem >> 6, d = rem & 63;
                float2 v2 = make_float2(acc[mi][ni][rr * 2], acc[mi][ni][rr * 2 + 1]);
                *(float2*)&dstbase[(((size_t)(b * HH + h)) * TT + tloc) * DD + d] = v2;
            }
        }
    }
}

__global__ __launch_bounds__(256, 2) void proj_mma_kernel(
    const float* __restrict__ w, const float* __restrict__ bias,
    float* __restrict__ out)
{
    __shared__ GemmSmem sm;
    const int bx = blockIdx.x;
    const int by = blockIdx.y;
    const int tid = threadIdx.x;
    const int wid = tid >> 5, lane = tid & 31;
    const int warp_m = wid & 3, warp_n = wid >> 2;
    const int g = lane >> 2, t = lane & 3;

    float acc[2][8][4];
    gemm_tf32_mainloop(&sm, g_y + (size_t)(by * 128) * CC, CC,
                       w + bx * 128, CC, acc);

    #pragma unroll
    for (int mi = 0; mi < 2; mi++) {
        #pragma unroll
        for (int rr = 0; rr < 2; rr++) {
            int m = by * 128 + warp_m * 32 + mi * 16 + g + rr * 8;
            #pragma unroll
            for (int ni = 0; ni < 8; ni++) {
                int n = bx * 128 + warp_n * 64 + ni * 8 + 2 * t;
                float2 v2;
                v2.x = acc[mi][ni][rr * 2]     + bias[n];
                v2.y = acc[mi][ni][rr * 2 + 1] + bias[n + 1];
                *(float2*)&out[(size_t)m * CC + n] = v2;
            }
        }
    }
}

// ===========================================================================
// Flash attention with tf32 mma.sync.
// CTA: 128 query rows of one (b,h). 8 warps x 16 rows. Key tiles of 64.
// Smem: Ks [64 d][64 key] XOR-swizzled (key ^ 8*(d&3)); Vs [64 key][72 d];
//       Ps [128 q][72] (staging for Q frags, then P tiles).
// ===========================================================================
#define QTILE 128
#define KTILE 64
#define SP 72
#define FA_SMEM_U32 (64*64 + 64*SP + 128*SP)
#define FA_SMEM_BYTES (FA_SMEM_U32 * 4)

__global__ __launch_bounds__(256) void flash_attn_mma_kernel()
{
    extern __shared__ uint32_t smu[];
    uint32_t* Ks = smu;              // [64][64] (d, key^8(d&3)) tf32
    uint32_t* Vs = Ks + 64 * 64;     // [64][SP] (key, d) tf32
    uint32_t* Ps = Vs + 64 * SP;     // [128][SP] Q staging, then P

    const int qi = blockIdx.x;       // 0..15
    const int bh = blockIdx.y;       // 0..31
    const int b = bh >> 4, h = bh & 15;
    const int tid = threadIdx.x;
    const int wid = tid >> 5, lane = tid & 31;
    const int g = lane >> 2, t = lane & 3;
    const int wbase = wid * 16;

    // ---- Stage Q tile into Ps, then pull A-fragments into registers ----
    const float* qptr = g_q + ((size_t)bh * TT + qi * QTILE) * DD;
    #pragma unroll
    for (int u = 0; u < 8; u++) {
        int f = u * 256 + tid;              // 0..2047 float4s
        int row = f >> 4, c4 = (f & 15) * 4;
        float4 v = ((const float4*)qptr)[f];
        uint32_t* p = &Ps[row * SP + c4];
        p[0] = f2tf32(v.x); p[1] = f2tf32(v.y);
        p[2] = f2tf32(v.z); p[3] = f2tf32(v.w);
    }
    __syncthreads();

    uint32_t qf[8][4];
    #pragma unroll
    for (int ks = 0; ks < 8; ks++) {
        qf[ks][0] = Ps[(wbase + g) * SP + ks * 8 + t];
        qf[ks][1] = Ps[(wbase + g + 8) * SP + ks * 8 + t];
        qf[ks][2] = Ps[(wbase + g) * SP + ks * 8 + t + 4];
        qf[ks][3] = Ps[(wbase + g + 8) * SP + ks * 8 + t + 4];
    }

    float of[8][4];
    #pragma unroll
    for (int nf = 0; nf < 8; nf++)
        #pragma unroll
        for (int r = 0; r < 4; r++) of[nf][r] = 0.f;
    float m0 = -1e30f, m1 = -1e30f, l0 = 0.f, l1 = 0.f;

    const int qrow0 = qi * QTILE + wbase + g;
    const int qrow1 = qrow0 + 8;

    const int nkt = 2 * qi + 2;
    for (int kt = 0; kt < nkt; kt++) {
        __syncthreads();   // Ks/Vs reads from previous iteration done

        // K tile: gmem [key][d] -> Ks[d][key ^ 8*(d&3)] (conflict-free stores)
        const float* kp = g_k + ((size_t)bh * TT + kt * KTILE) * DD;
        const float* vp = g_v + ((size_t)bh * TT + kt * KTILE) * DD;
        #pragma unroll
        for (int u = 0; u < 4; u++) {
            int f = u * 256 + tid;          // 0..1023 float4s
            {
                int key = f & 63;
                int c4 = (f >> 6) * 4;      // d base
                float4 kv = *(const float4*)(kp + (size_t)key * DD + c4);
                Ks[(c4 + 0) * 64 + (key ^ (((c4 + 0) & 3) * 8))] = f2tf32(kv.x);
                Ks[(c4 + 1) * 64 + (key ^ (((c4 + 1) & 3) * 8))] = f2tf32(kv.y);
                Ks[(c4 + 2) * 64 + (key ^ (((c4 + 2) & 3) * 8))] = f2tf32(kv.z);
                Ks[(c4 + 3) * 64 + (key ^ (((c4 + 3) & 3) * 8))] = f2tf32(kv.w);
            }
            {
                int row = f >> 4, c4 = (f & 15) * 4;
                float4 vv = *(const float4*)(vp + (size_t)row * DD + c4);
                uint32_t* p = &Vs[row * SP + c4];
                p[0] = f2tf32(vv.x); p[1] = f2tf32(vv.y);
                p[2] = f2tf32(vv.z); p[3] = f2tf32(vv.w);
            }
        }
        __syncthreads();

        // ---- S = Q @ K^T (per warp: 16x64) ----
        float sf[8][4];
        #pragma unroll
        for (int nf = 0; nf < 8; nf++)
            #pragma unroll
            for (int r = 0; r < 4; r++) sf[nf][r] = 0.f;

        #pragma unroll
        for (int ks = 0; ks < 8; ks++) {
            const int r0 = (8 * ks + t) * 64;
            const int r1 = (8 * ks + t + 4) * 64;
            #pragma unroll
            for (int nf = 0; nf < 8; nf++) {
                const int keyx = (nf * 8 + g) ^ (8 * t);   // d&3 == t for both rows
                uint32_t bf[2] = { Ks[r0 + keyx], Ks[r1 + keyx] };
                mma_tf32_16x8x8(sf[nf], qf[ks], bf);
            }
        }

        // ---- scale + causal mask ----
        const bool need_mask = (kt >= 2 * qi);
        #pragma unroll
        for (int nf = 0; nf < 8; nf++) {
            int kc0 = kt * KTILE + nf * 8 + 2 * t;
            int kc1 = kc0 + 1;
            if (need_mask) {
                sf[nf][0] = (kc0 <= qrow0) ? sf[nf][0] * SCALE : -1e30f;
                sf[nf][1] = (kc1 <= qrow0) ? sf[nf][1] * SCALE : -1e30f;
                sf[nf][2] = (kc0 <= qrow1) ? sf[nf][2] * SCALE : -1e30f;
                sf[nf][3] = (kc1 <= qrow1) ? sf[nf][3] * SCALE : -1e30f;
            } else {
                sf[nf][0] *= SCALE; sf[nf][1] *= SCALE;
                sf[nf][2] *= SCALE; sf[nf][3] *= SCALE;
            }
        }

        // ---- online softmax ----
        float mx0 = -1e30f, mx1 = -1e30f;
        #pragma unroll
        for (int nf = 0; nf < 8; nf++) {
            mx0 = fmaxf(mx0, fmaxf(sf[nf][0], sf[nf][1]));
            mx1 = fmaxf(mx1, fmaxf(sf[nf][2], sf[nf][3]));
        }
        #pragma unroll
        for (int off = 1; off < 4; off <<= 1) {
            mx0 = fmaxf(mx0, __shfl_xor_sync(0xffffffffu, mx0, off));
            mx1 = fmaxf(mx1, __shfl_xor_sync(0xffffffffu, mx1, off));
        }
        float mn0 = fmaxf(m0, mx0), mn1 = fmaxf(m1, mx1);
        float a0 = __expf(m0 - mn0), a1 = __expf(m1 - mn1);
        m0 = mn0; m1 = mn1;

        float s0 = 0.f, s1 = 0.f;
        #pragma unroll
        for (int nf = 0; nf < 8; nf++) {
            sf[nf][0] = __expf(sf[nf][0] - mn0);
            sf[nf][1] = __expf(sf[nf][1] - mn0);
            sf[nf][2] = __expf(sf[nf][2] - mn1);
            sf[nf][3] = __expf(sf[nf][3] - mn1);
            s0 += sf[nf][0] + sf[nf][1];
            s1 += sf[nf][2] + sf[nf][3];
        }
        #pragma unroll
        for (int off = 1; off < 4; off <<= 1) {
            s0 += __shfl_xor_sync(0xffffffffu, s0, off);
            s1 += __shfl_xor_sync(0xffffffffu, s1, off);
        }
        l0 = l0 * a0 + s0;
        l1 = l1 * a1 + s1;

        #pragma unroll
        for (int nf = 0; nf < 8; nf++) {
            of[nf][0] *= a0; of[nf][1] *= a0;
            of[nf][2] *= a1; of[nf][3] *= a1;
        }

        // ---- store P (warp-local region of Ps) ----
        __syncwarp();
        #pragma unroll
        for (int nf = 0; nf < 8; nf++) {
            uint2 p01 = make_uint2(f2tf32(sf[nf][0]), f2tf32(sf[nf][1]));
            uint2 p23 = make_uint2(f2tf32(sf[nf][2]), f2tf32(sf[nf][3]));
            *(uint2*)&Ps[(wbase + g) * SP + nf * 8 + 2 * t]     = p01;
            *(uint2*)&Ps[(wbase + g + 8) * SP + nf * 8 + 2 * t] = p23;
        }
        __syncwarp();

        // ---- O += P @ V ----
        #pragma unroll
        for (int ks = 0; ks < 8; ks++) {
            uint32_t af[4];
            af[0] = Ps[(wbase + g) * SP + ks * 8 + t];
            af[1] = Ps[(wbase + g + 8) * SP + ks * 8 + t];
            af[2] = Ps[(wbase + g) * SP + ks * 8 + t + 4];
            af[3] = Ps[(wbase + g + 8) * SP + ks * 8 + t + 4];
            const int r0 = (8 * ks + t) * SP;
            const int r1 = (8 * ks + t + 4) * SP;
            #pragma unroll
            for (int nf = 0; nf < 8; nf++) {
                uint32_t bf[2] = { Vs[r0 + nf * 8 + g], Vs[r1 + nf * 8 + g] };
                mma_tf32_16x8x8(of[nf], af, bf);
            }
        }
    }

    // ---- epilogue: normalize and write y ----
    float inv0 = 1.f / l0, inv1 = 1.f / l1;
    const int t0 = qi * QTILE + wbase + g;
    const int t1 = t0 + 8;
    float* y0 = g_y + ((size_t)b * TT + t0) * CC + h * DD;
    float* y1 = g_y + ((size_t)b * TT + t1) * CC + h * DD;
    #pragma unroll
    for (int nf = 0; nf < 8; nf++) {
        int d = nf * 8 + 2 * t;
        *(float2*)&y0[d] = make_float2(of[nf][0] * inv0, of[nf][1] * inv0);
        *(float2*)&y1[d] = make_float2(of[nf][2] * inv1, of[nf][3] * inv1);
    }
}

// ---------------------------------------------------------------------------
extern "C" void kernel_launch(void* const* d_in, const int* in_sizes, int n_in,
                              void* d_out, int out_size)
{
    const float* x      = (const float*)d_in[0];
    const float* w_qkv  = (const float*)d_in[1];
    const float* w_proj = (const float*)d_in[2];
    const float* b_proj = (const float*)d_in[3];
    float* out = (float*)d_out;

    static bool attr_set = false;
    if (!attr_set) {
        cudaFuncSetAttribute(flash_attn_mma_kernel,
                             cudaFuncAttributeMaxDynamicSharedMemorySize,
                             FA_SMEM_BYTES);
        attr_set = true;
    }

    {
        dim3 grid(3*CC/128, MROWS/128);   // (24, 32)
        qkv_mma_kernel<<<grid, 256>>>(x, w_qkv);
    }
    {
        dim3 grid(TT/QTILE, BB*HH);       // (16, 32)
        flash_attn_mma_kernel<<<grid, 256, FA_SMEM_BYTES>>>();
    }
    {
        dim3 grid(CC/128, MROWS/128);     // (8, 32)
        proj_mma_kernel<<<grid, 256>>>(w_proj, b_proj, out);
    }
}

// round 7
// speedup vs baseline: 3.2301x; 1.1130x over previous
#include <cuda_runtime.h>
#include <cuda_bf16.h>
#include <cstdint>

// Problem constants
#define BB   2
#define TT   2048
#define CC   1024
#define HH   16
#define DD   64
#define MROWS (BB*TT)          // 4096
#define SCALE 0.125f           // 1/sqrt(64)

// Scratch (device globals — no allocations allowed)
__device__ float g_q[BB*HH*TT*DD];   // [B*H, T, D]
__device__ float g_k[BB*HH*TT*DD];
__device__ float g_v[BB*HH*TT*DD];
__device__ float g_y[BB*TT*CC];      // [B, T, C] attention output

// ===========================================================================
// tf32 mma.sync helpers (sm_80+ path — compiles for plain sm_103)
// ===========================================================================
__device__ __forceinline__ uint32_t f2tf32(float x) {
    uint32_t y;
    asm("cvt.rna.tf32.f32 %0, %1;" : "=r"(y) : "f"(x));
    return y;
}

__device__ __forceinline__ void mma_tf32_16x8x8(float* c, const uint32_t* a,
                                                const uint32_t* b) {
    asm volatile(
        "mma.sync.aligned.m16n8k8.row.col.f32.tf32.tf32.f32 "
        "{%0,%1,%2,%3}, {%4,%5,%6,%7}, {%8,%9}, {%0,%1,%2,%3};\n"
        : "+f"(c[0]), "+f"(c[1]), "+f"(c[2]), "+f"(c[3])
        : "r"(a[0]), "r"(a[1]), "r"(a[2]), "r"(a[3]),
          "r"(b[0]), "r"(b[1]));
}

// ===========================================================================
// Pipelined tf32 GEMM mainloop. CTA = 128x128 tile, 128 threads (4 warps),
// warp tile 64x64. 2-stage smem double-buffer, register prefetch,
// ONE __syncthreads per 32-wide K chunk.
//   A smem pitch 36: frag addr (4g+t) mod 32 -> conflict-free
//   B smem pitch 132: frag addr (4t+g) mod 32 -> conflict-free
// ===========================================================================
#define AP 36
#define BPITCH 132
#define STAGE_U32 (128*AP + 32*BPITCH)         // 8832 u32 per stage
#define GEMM_SMEM_BYTES (2 * STAGE_U32 * 4)    // 70656 B

__device__ __forceinline__ void gemm_tf32_mainloop_pipe(
    uint32_t* sm, const float* __restrict__ A, int lda,
    const float* __restrict__ B, int ldb, float acc[4][8][4])
{
    const int tid = threadIdx.x;
    const int wid = tid >> 5;
    const int lane = tid & 31;
    const int warp_m = wid & 1;          // 2 warps along M (64 rows)
    const int warp_n = wid >> 1;         // 2 warps along N (64 cols)
    const int g = lane >> 2;
    const int t = lane & 3;

    #pragma unroll
    for (int mi = 0; mi < 4; mi++)
        #pragma unroll
        for (int ni = 0; ni < 8; ni++)
            #pragma unroll
            for (int r = 0; r < 4; r++) acc[mi][ni][r] = 0.f;

    // Per-thread gmem staging registers for one chunk
    float4 ra[8], rb[8];
    const int arow = tid >> 3, acv = tid & 7;        // A: 8 f4-rows per thread-row
    const int brow = tid >> 5, bcv = tid & 31;       // B: per-thread k-row/col

    // ---- prologue: chunk 0 ----
    #pragma unroll
    for (int u = 0; u < 8; u++)
        ra[u] = *(const float4*)(A + (size_t)(u * 16 + arow) * lda + acv * 4);
    #pragma unroll
    for (int u = 0; u < 8; u++)
        rb[u] = *(const float4*)(B + (size_t)(u * 4 + brow) * ldb + bcv * 4);

    {
        uint32_t* As = sm;
        uint32_t* Bs = sm + 128 * AP;
        #pragma unroll
        for (int u = 0; u < 8; u++) {
            uint32_t* p = &As[(u * 16 + arow) * AP + acv * 4];
            p[0] = f2tf32(ra[u].x); p[1] = f2tf32(ra[u].y);
            p[2] = f2tf32(ra[u].z); p[3] = f2tf32(ra[u].w);
        }
        #pragma unroll
        for (int u = 0; u < 8; u++) {
            uint32_t* p = &Bs[(u * 4 + brow) * BPITCH + bcv * 4];
            p[0] = f2tf32(rb[u].x); p[1] = f2tf32(rb[u].y);
            p[2] = f2tf32(rb[u].z); p[3] = f2tf32(rb[u].w);
        }
    }
    __syncthreads();

    for (int c = 0; c < CC / 32; c++) {
        // ---- prefetch chunk c+1 into registers (hidden behind MMA) ----
        if (c < CC / 32 - 1) {
            const float* An = A + (c + 1) * 32;
            const float* Bn = B + (size_t)((c + 1) * 32) * ldb;
            #pragma unroll
            for (int u = 0; u < 8; u++)
                ra[u] = *(const float4*)(An + (size_t)(u * 16 + arow) * lda + acv * 4);
            #pragma unroll
            for (int u = 0; u < 8; u++)
                rb[u] = *(const float4*)(Bn + (size_t)(u * 4 + brow) * ldb + bcv * 4);
        }

        // ---- compute on stage c&1 ----
        uint32_t* As = sm + (c & 1) * STAGE_U32;
        uint32_t* Bs = As + 128 * AP;
        #pragma unroll
        for (int ks = 0; ks < 4; ks++) {
            const int k0 = ks * 8;
            uint32_t af[4][4];
            #pragma unroll
            for (int mi = 0; mi < 4; mi++) {
                int mb = warp_m * 64 + mi * 16;
                af[mi][0] = As[(mb + g) * AP + k0 + t];
                af[mi][1] = As[(mb + g + 8) * AP + k0 + t];
                af[mi][2] = As[(mb + g) * AP + k0 + t + 4];
                af[mi][3] = As[(mb + g + 8) * AP + k0 + t + 4];
            }
            uint32_t bf[8][2];
            #pragma unroll
            for (int ni = 0; ni < 8; ni++) {
                int nb = warp_n * 64 + ni * 8;
                bf[ni][0] = Bs[(k0 + t) * BPITCH + nb + g];
                bf[ni][1] = Bs[(k0 + t + 4) * BPITCH + nb + g];
            }
            #pragma unroll
            for (int mi = 0; mi < 4; mi++)
                #pragma unroll
                for (int ni = 0; ni < 8; ni++)
                    mma_tf32_16x8x8(acc[mi][ni], af[mi], bf[ni]);
        }

        // ---- store chunk c+1 into the other stage (safe: last read ended
        //      at the sync closing iteration c-1) ----
        if (c < CC / 32 - 1) {
            uint32_t* As2 = sm + ((c + 1) & 1) * STAGE_U32;
            uint32_t* Bs2 = As2 + 128 * AP;
            #pragma unroll
            for (int u = 0; u < 8; u++) {
                uint32_t* p = &As2[(u * 16 + arow) * AP + acv * 4];
                p[0] = f2tf32(ra[u].x); p[1] = f2tf32(ra[u].y);
                p[2] = f2tf32(ra[u].z); p[3] = f2tf32(ra[u].w);
            }
            #pragma unroll
            for (int u = 0; u < 8; u++) {
                uint32_t* p = &Bs2[(u * 4 + brow) * BPITCH + bcv * 4];
                p[0] = f2tf32(rb[u].x); p[1] = f2tf32(rb[u].y);
                p[2] = f2tf32(rb[u].z); p[3] = f2tf32(rb[u].w);
            }
        }
        __syncthreads();
    }
}

// ---------------------------------------------------------------------------
// Kernel 1: QKV projection + scatter to g_q/g_k/g_v
// grid (24, 32), block 128
// ---------------------------------------------------------------------------
__global__ __launch_bounds__(128, 2) void qkv_mma_kernel(
    const float* __restrict__ x, const float* __restrict__ w)
{
    extern __shared__ uint32_t smu[];
    const int bx = blockIdx.x;   // N tile of 3072 (0..23)
    const int by = blockIdx.y;   // M tile (0..31)
    const int tid = threadIdx.x;
    const int wid = tid >> 5, lane = tid & 31;
    const int warp_m = wid & 1, warp_n = wid >> 1;
    const int g = lane >> 2, t = lane & 3;

    float acc[4][8][4];
    gemm_tf32_mainloop_pipe(smu, x + (size_t)(by * 128) * CC, CC,
                            w + bx * 128, 3 * CC, acc);

    const int g3 = bx >> 3;
    float* dstbase = (g3 == 0) ? g_q : (g3 == 1) ? g_k : g_v;

    #pragma unroll
    for (int mi = 0; mi < 4; mi++) {
        #pragma unroll
        for (int rr = 0; rr < 2; rr++) {
            int m = by * 128 + warp_m * 64 + mi * 16 + g + rr * 8;
            int b = m >> 11, tloc = m & (TT - 1);
            #pragma unroll
            for (int ni = 0; ni < 8; ni++) {
                int n = bx * 128 + warp_n * 64 + ni * 8 + 2 * t;
                int rem = n & 1023;
                int h = rem >> 6, d = rem & 63;
                float2 v2 = make_float2(acc[mi][ni][rr * 2], acc[mi][ni][rr * 2 + 1]);
                *(float2*)&dstbase[(((size_t)(b * HH + h)) * TT + tloc) * DD + d] = v2;
            }
        }
    }
}

// ---------------------------------------------------------------------------
// Kernel 3: out = y @ w_proj + b_proj
// grid (8, 32), block 128
// ---------------------------------------------------------------------------
__global__ __launch_bounds__(128, 2) void proj_mma_kernel(
    const float* __restrict__ w, const float* __restrict__ bias,
    float* __restrict__ out)
{
    extern __shared__ uint32_t smu[];
    const int bx = blockIdx.x;
    const int by = blockIdx.y;
    const int tid = threadIdx.x;
    const int wid = tid >> 5, lane = tid & 31;
    const int warp_m = wid & 1, warp_n = wid >> 1;
    const int g = lane >> 2, t = lane & 3;

    float acc[4][8][4];
    gemm_tf32_mainloop_pipe(smu, g_y + (size_t)(by * 128) * CC, CC,
                            w + bx * 128, CC, acc);

    #pragma unroll
    for (int mi = 0; mi < 4; mi++) {
        #pragma unroll
        for (int rr = 0; rr < 2; rr++) {
            int m = by * 128 + warp_m * 64 + mi * 16 + g + rr * 8;
            #pragma unroll
            for (int ni = 0; ni < 8; ni++) {
                int n = bx * 128 + warp_n * 64 + ni * 8 + 2 * t;
                float2 v2;
                v2.x = acc[mi][ni][rr * 2]     + bias[n];
                v2.y = acc[mi][ni][rr * 2 + 1] + bias[n + 1];
                *(float2*)&out[(size_t)m * CC + n] = v2;
            }
        }
    }
}

// ===========================================================================
// Flash attention with tf32 mma.sync (unchanged from R6 passing version).
// ===========================================================================
#define QTILE 128
#define KTILE 64
#define SP 72
#define FA_SMEM_U32 (64*64 + 64*SP + 128*SP)
#define FA_SMEM_BYTES (FA_SMEM_U32 * 4)

__global__ __launch_bounds__(256) void flash_attn_mma_kernel()
{
    extern __shared__ uint32_t smu[];
    uint32_t* Ks = smu;              // [64][64] (d, key^8(d&3)) tf32
    uint32_t* Vs = Ks + 64 * 64;     // [64][SP] (key, d) tf32
    uint32_t* Ps = Vs + 64 * SP;     // [128][SP] Q staging, then P

    const int qi = blockIdx.x;       // 0..15
    const int bh = blockIdx.y;       // 0..31
    const int b = bh >> 4, h = bh & 15;
    const int tid = threadIdx.x;
    const int wid = tid >> 5, lane = tid & 31;
    const int g = lane >> 2, t = lane & 3;
    const int wbase = wid * 16;

    const float* qptr = g_q + ((size_t)bh * TT + qi * QTILE) * DD;
    #pragma unroll
    for (int u = 0; u < 8; u++) {
        int f = u * 256 + tid;
        int row = f >> 4, c4 = (f & 15) * 4;
        float4 v = ((const float4*)qptr)[f];
        uint32_t* p = &Ps[row * SP + c4];
        p[0] = f2tf32(v.x); p[1] = f2tf32(v.y);
        p[2] = f2tf32(v.z); p[3] = f2tf32(v.w);
    }
    __syncthreads();

    uint32_t qf[8][4];
    #pragma unroll
    for (int ks = 0; ks < 8; ks++) {
        qf[ks][0] = Ps[(wbase + g) * SP + ks * 8 + t];
        qf[ks][1] = Ps[(wbase + g + 8) * SP + ks * 8 + t];
        qf[ks][2] = Ps[(wbase + g) * SP + ks * 8 + t + 4];
        qf[ks][3] = Ps[(wbase + g + 8) * SP + ks * 8 + t + 4];
    }

    float of[8][4];
    #pragma unroll
    for (int nf = 0; nf < 8; nf++)
        #pragma unroll
        for (int r = 0; r < 4; r++) of[nf][r] = 0.f;
    float m0 = -1e30f, m1 = -1e30f, l0 = 0.f, l1 = 0.f;

    const int qrow0 = qi * QTILE + wbase + g;
    const int qrow1 = qrow0 + 8;

    const int nkt = 2 * qi + 2;
    for (int kt = 0; kt < nkt; kt++) {
        __syncthreads();

        const float* kp = g_k + ((size_t)bh * TT + kt * KTILE) * DD;
        const float* vp = g_v + ((size_t)bh * TT + kt * KTILE) * DD;
        #pragma unroll
        for (int u = 0; u < 4; u++) {
            int f = u * 256 + tid;
            {
                int key = f & 63;
                int c4 = (f >> 6) * 4;
                float4 kv = *(const float4*)(kp + (size_t)key * DD + c4);
                Ks[(c4 + 0) * 64 + (key ^ (((c4 + 0) & 3) * 8))] = f2tf32(kv.x);
                Ks[(c4 + 1) * 64 + (key ^ (((c4 + 1) & 3) * 8))] = f2tf32(kv.y);
                Ks[(c4 + 2) * 64 + (key ^ (((c4 + 2) & 3) * 8))] = f2tf32(kv.z);
                Ks[(c4 + 3) * 64 + (key ^ (((c4 + 3) & 3) * 8))] = f2tf32(kv.w);
            }
            {
                int row = f >> 4, c4 = (f & 15) * 4;
                float4 vv = *(const float4*)(vp + (size_t)row * DD + c4);
                uint32_t* p = &Vs[row * SP + c4];
                p[0] = f2tf32(vv.x); p[1] = f2tf32(vv.y);
                p[2] = f2tf32(vv.z); p[3] = f2tf32(vv.w);
            }
        }
        __syncthreads();

        float sf[8][4];
        #pragma unroll
        for (int nf = 0; nf < 8; nf++)
            #pragma unroll
            for (int r = 0; r < 4; r++) sf[nf][r] = 0.f;

        #pragma unroll
        for (int ks = 0; ks < 8; ks++) {
            const int r0 = (8 * ks + t) * 64;
            const int r1 = (8 * ks + t + 4) * 64;
            #pragma unroll
            for (int nf = 0; nf < 8; nf++) {
                const int keyx = (nf * 8 + g) ^ (8 * t);
                uint32_t bf[2] = { Ks[r0 + keyx], Ks[r1 + keyx] };
                mma_tf32_16x8x8(sf[nf], qf[ks], bf);
            }
        }

        const bool need_mask = (kt >= 2 * qi);
        #pragma unroll
        for (int nf = 0; nf < 8; nf++) {
            int kc0 = kt * KTILE + nf * 8 + 2 * t;
            int kc1 = kc0 + 1;
            if (need_mask) {
                sf[nf][0] = (kc0 <= qrow0) ? sf[nf][0] * SCALE : -1e30f;
                sf[nf][1] = (kc1 <= qrow0) ? sf[nf][1] * SCALE : -1e30f;
                sf[nf][2] = (kc0 <= qrow1) ? sf[nf][2] * SCALE : -1e30f;
                sf[nf][3] = (kc1 <= qrow1) ? sf[nf][3] * SCALE : -1e30f;
            } else {
                sf[nf][0] *= SCALE; sf[nf][1] *= SCALE;
                sf[nf][2] *= SCALE; sf[nf][3] *= SCALE;
            }
        }

        float mx0 = -1e30f, mx1 = -1e30f;
        #pragma unroll
        for (int nf = 0; nf < 8; nf++) {
            mx0 = fmaxf(mx0, fmaxf(sf[nf][0], sf[nf][1]));
            mx1 = fmaxf(mx1, fmaxf(sf[nf][2], sf[nf][3]));
        }
        #pragma unroll
        for (int off = 1; off < 4; off <<= 1) {
            mx0 = fmaxf(mx0, __shfl_xor_sync(0xffffffffu, mx0, off));
            mx1 = fmaxf(mx1, __shfl_xor_sync(0xffffffffu, mx1, off));
        }
        float mn0 = fmaxf(m0, mx0), mn1 = fmaxf(m1, mx1);
        float a0 = __expf(m0 - mn0), a1 = __expf(m1 - mn1);
        m0 = mn0; m1 = mn1;

        float s0 = 0.f, s1 = 0.f;
        #pragma unroll
        for (int nf = 0; nf < 8; nf++) {
            sf[nf][0] = __expf(sf[nf][0] - mn0);
            sf[nf][1] = __expf(sf[nf][1] - mn0);
            sf[nf][2] = __expf(sf[nf][2] - mn1);
            sf[nf][3] = __expf(sf[nf][3] - mn1);
            s0 += sf[nf][0] + sf[nf][1];
            s1 += sf[nf][2] + sf[nf][3];
        }
        #pragma unroll
        for (int off = 1; off < 4; off <<= 1) {
            s0 += __shfl_xor_sync(0xffffffffu, s0, off);
            s1 += __shfl_xor_sync(0xffffffffu, s1, off);
        }
        l0 = l0 * a0 + s0;
        l1 = l1 * a1 + s1;

        #pragma unroll
        for (int nf = 0; nf < 8; nf++) {
            of[nf][0] *= a0; of[nf][1] *= a0;
            of[nf][2] *= a1; of[nf][3] *= a1;
        }

        __syncwarp();
        #pragma unroll
        for (int nf = 0; nf < 8; nf++) {
            uint2 p01 = make_uint2(f2tf32(sf[nf][0]), f2tf32(sf[nf][1]));
            uint2 p23 = make_uint2(f2tf32(sf[nf][2]), f2tf32(sf[nf][3]));
            *(uint2*)&Ps[(wbase + g) * SP + nf * 8 + 2 * t]     = p01;
            *(uint2*)&Ps[(wbase + g + 8) * SP + nf * 8 + 2 * t] = p23;
        }
        __syncwarp();

        #pragma unroll
        for (int ks = 0; ks < 8; ks++) {
            uint32_t af[4];
            af[0] = Ps[(wbase + g) * SP + ks * 8 + t];
            af[1] = Ps[(wbase + g + 8) * SP + ks * 8 + t];
            af[2] = Ps[(wbase + g) * SP + ks * 8 + t + 4];
            af[3] = Ps[(wbase + g + 8) * SP + ks * 8 + t + 4];
            const int r0 = (8 * ks + t) * SP;
            const int r1 = (8 * ks + t + 4) * SP;
            #pragma unroll
            for (int nf = 0; nf < 8; nf++) {
                uint32_t bf[2] = { Vs[r0 + nf * 8 + g], Vs[r1 + nf * 8 + g] };
                mma_tf32_16x8x8(of[nf], af, bf);
            }
        }
    }

    float inv0 = 1.f / l0, inv1 = 1.f / l1;
    const int t0 = qi * QTILE + wbase + g;
    const int t1 = t0 + 8;
    float* y0 = g_y + ((size_t)b * TT + t0) * CC + h * DD;
    float* y1 = g_y + ((size_t)b * TT + t1) * CC + h * DD;
    #pragma unroll
    for (int nf = 0; nf < 8; nf++) {
        int d = nf * 8 + 2 * t;
        *(float2*)&y0[d] = make_float2(of[nf][0] * inv0, of[nf][1] * inv0);
        *(float2*)&y1[d] = make_float2(of[nf][2] * inv1, of[nf][3] * inv1);
    }
}

// ---------------------------------------------------------------------------
extern "C" void kernel_launch(void* const* d_in, const int* in_sizes, int n_in,
                              void* d_out, int out_size)
{
    const float* x      = (const float*)d_in[0];
    const float* w_qkv  = (const float*)d_in[1];
    const float* w_proj = (const float*)d_in[2];
    const float* b_proj = (const float*)d_in[3];
    float* out = (float*)d_out;

    static bool attr_set = false;
    if (!attr_set) {
        cudaFuncSetAttribute(flash_attn_mma_kernel,
                             cudaFuncAttributeMaxDynamicSharedMemorySize,
                             FA_SMEM_BYTES);
        cudaFuncSetAttribute(qkv_mma_kernel,
                             cudaFuncAttributeMaxDynamicSharedMemorySize,
                             GEMM_SMEM_BYTES);
        cudaFuncSetAttribute(proj_mma_kernel,
                             cudaFuncAttributeMaxDynamicSharedMemorySize,
                             GEMM_SMEM_BYTES);
        attr_set = true;
    }

    {
        dim3 grid(3*CC/128, MROWS/128);   // (24, 32)
        qkv_mma_kernel<<<grid, 128, GEMM_SMEM_BYTES>>>(x, w_qkv);
    }
    {
        dim3 grid(TT/QTILE, BB*HH);       // (16, 32)
        flash_attn_mma_kernel<<<grid, 256, FA_SMEM_BYTES>>>();
    }
    {
        dim3 grid(CC/128, MROWS/128);     // (8, 32)
        proj_mma_kernel<<<grid, 128, GEMM_SMEM_BYTES>>>(w_proj, b_proj, out);
    }
}

// round 9
// speedup vs baseline: 3.2817x; 1.0160x over previous
#include <cuda_runtime.h>
#include <cuda_bf16.h>
#include <cstdint>

// Problem constants
#define BB   2
#define TT   2048
#define CC   1024
#define HH   16
#define DD   64
#define MROWS (BB*TT)          // 4096
#define SCALE 0.125f           // 1/sqrt(64)

// Scratch (device globals — no allocations allowed). All tf32 bit patterns.
__device__ uint32_t g_xt[MROWS*CC];        // x as tf32 bits
__device__ uint32_t g_wqt[CC*3*CC];        // w_qkv as tf32 bits
__device__ uint32_t g_wpt[CC*CC];          // w_proj as tf32 bits
__device__ uint32_t g_q[BB*HH*TT*DD];      // [B*H, T, D] tf32 bits
__device__ uint32_t g_k[BB*HH*TT*DD];
__device__ uint32_t g_v[BB*HH*TT*DD];
__device__ uint32_t g_y[BB*TT*CC];         // [B, T, C] attention out, tf32 bits

// ===========================================================================
// helpers
// ===========================================================================
__device__ __forceinline__ uint32_t f2tf32(float x) {
    uint32_t y;
    asm("cvt.rna.tf32.f32 %0, %1;" : "=r"(y) : "f"(x));
    return y;
}

__device__ __forceinline__ void mma_tf32_16x8x8(float* c, const uint32_t* a,
                                                const uint32_t* b) {
    asm volatile(
        "mma.sync.aligned.m16n8k8.row.col.f32.tf32.tf32.f32 "
        "{%0,%1,%2,%3}, {%4,%5,%6,%7}, {%8,%9}, {%0,%1,%2,%3};\n"
        : "+f"(c[0]), "+f"(c[1]), "+f"(c[2]), "+f"(c[3])
        : "r"(a[0]), "r"(a[1]), "r"(a[2]), "r"(a[3]),
          "r"(b[0]), "r"(b[1]));
}

// ---------------------------------------------------------------------------
// Kernel 0: fp32 -> tf32-bits bulk convert (bandwidth bound)
// ---------------------------------------------------------------------------
__global__ __launch_bounds__(256) void conv_tf32_kernel(
    const float4* __restrict__ in, uint4* __restrict__ out, int n4)
{
    int i = blockIdx.x * blockDim.x + threadIdx.x;
    int stride = gridDim.x * blockDim.x;
    for (; i < n4; i += stride) {
        float4 v = in[i];
        uint4 o;
        o.x = f2tf32(v.x); o.y = f2tf32(v.y);
        o.z = f2tf32(v.z); o.w = f2tf32(v.w);
        out[i] = o;
    }
}

// ===========================================================================
// Pipelined tf32 GEMM mainloop. CTA = 128x128 tile, 128 threads (4 warps),
// warp tile 64x64. 2-stage smem double-buffer, register prefetch,
// ONE __syncthreads per 32-wide K chunk. Inputs already tf32 bits.
// ===========================================================================
#define AP 36
#define BPITCH 132
#define STAGE_U32 (128*AP + 32*BPITCH)         // 8832 u32 per stage
#define GEMM_SMEM_BYTES (2 * STAGE_U32 * 4)    // 70656 B

__device__ __forceinline__ void gemm_tf32_mainloop_pipe(
    uint32_t* sm, const uint32_t* __restrict__ A, int lda,
    const uint32_t* __restrict__ B, int ldb, float acc[4][8][4])
{
    const int tid = threadIdx.x;
    const int wid = tid >> 5;
    const int lane = tid & 31;
    const int warp_m = wid & 1;
    const int warp_n = wid >> 1;
    const int g = lane >> 2;
    const int t = lane & 3;

    #pragma unroll
    for (int mi = 0; mi < 4; mi++)
        #pragma unroll
        for (int ni = 0; ni < 8; ni++)
            #pragma unroll
            for (int r = 0; r < 4; r++) acc[mi][ni][r] = 0.f;

    uint4 ra[8], rb[8];
    const int arow = tid >> 3, acv = tid & 7;
    const int brow = tid >> 5, bcv = tid & 31;

    #pragma unroll
    for (int u = 0; u < 8; u++)
        ra[u] = *(const uint4*)(A + (size_t)(u * 16 + arow) * lda + acv * 4);
    #pragma unroll
    for (int u = 0; u < 8; u++)
        rb[u] = *(const uint4*)(B + (size_t)(u * 4 + brow) * ldb + bcv * 4);

    {
        uint32_t* As = sm;
        uint32_t* Bs = sm + 128 * AP;
        #pragma unroll
        for (int u = 0; u < 8; u++) {
            uint32_t* p = &As[(u * 16 + arow) * AP + acv * 4];
            p[0] = ra[u].x; p[1] = ra[u].y; p[2] = ra[u].z; p[3] = ra[u].w;
        }
        #pragma unroll
        for (int u = 0; u < 8; u++) {
            uint32_t* p = &Bs[(u * 4 + brow) * BPITCH + bcv * 4];
            p[0] = rb[u].x; p[1] = rb[u].y; p[2] = rb[u].z; p[3] = rb[u].w;
        }
    }
    __syncthreads();

    for (int c = 0; c < CC / 32; c++) {
        if (c < CC / 32 - 1) {
            const uint32_t* An = A + (c + 1) * 32;
            const uint32_t* Bn = B + (size_t)((c + 1) * 32) * ldb;
            #pragma unroll
            for (int u = 0; u < 8; u++)
                ra[u] = *(const uint4*)(An + (size_t)(u * 16 + arow) * lda + acv * 4);
            #pragma unroll
            for (int u = 0; u < 8; u++)
                rb[u] = *(const uint4*)(Bn + (size_t)(u * 4 + brow) * ldb + bcv * 4);
        }

        uint32_t* As = sm + (c & 1) * STAGE_U32;
        uint32_t* Bs = As + 128 * AP;
        #pragma unroll
        for (int ks = 0; ks < 4; ks++) {
            const int k0 = ks * 8;
            uint32_t af[4][4];
            #pragma unroll
            for (int mi = 0; mi < 4; mi++) {
                int mb = warp_m * 64 + mi * 16;
                af[mi][0] = As[(mb + g) * AP + k0 + t];
                af[mi][1] = As[(mb + g + 8) * AP + k0 + t];
                af[mi][2] = As[(mb + g) * AP + k0 + t + 4];
                af[mi][3] = As[(mb + g + 8) * AP + k0 + t + 4];
            }
            uint32_t bf[8][2];
            #pragma unroll
            for (int ni = 0; ni < 8; ni++) {
                int nb = warp_n * 64 + ni * 8;
                bf[ni][0] = Bs[(k0 + t) * BPITCH + nb + g];
                bf[ni][1] = Bs[(k0 + t + 4) * BPITCH + nb + g];
            }
            #pragma unroll
            for (int mi = 0; mi < 4; mi++)
                #pragma unroll
                for (int ni = 0; ni < 8; ni++)
                    mma_tf32_16x8x8(acc[mi][ni], af[mi], bf[ni]);
        }

        if (c < CC / 32 - 1) {
            uint32_t* As2 = sm + ((c + 1) & 1) * STAGE_U32;
            uint32_t* Bs2 = As2 + 128 * AP;
            #pragma unroll
            for (int u = 0; u < 8; u++) {
                uint32_t* p = &As2[(u * 16 + arow) * AP + acv * 4];
                p[0] = ra[u].x; p[1] = ra[u].y; p[2] = ra[u].z; p[3] = ra[u].w;
            }
            #pragma unroll
            for (int u = 0; u < 8; u++) {
                uint32_t* p = &Bs2[(u * 4 + brow) * BPITCH + bcv * 4];
                p[0] = rb[u].x; p[1] = rb[u].y; p[2] = rb[u].z; p[3] = rb[u].w;
            }
        }
        __syncthreads();
    }
}

// ---------------------------------------------------------------------------
// Kernel 1: QKV projection + scatter (tf32 bits out)
// ---------------------------------------------------------------------------
__global__ __launch_bounds__(128, 2) void qkv_mma_kernel()
{
    extern __shared__ uint32_t smu[];
    const int bx = blockIdx.x;   // 0..23
    const int by = blockIdx.y;   // 0..31
    const int tid = threadIdx.x;
    const int wid = tid >> 5, lane = tid & 31;
    const int warp_m = wid & 1, warp_n = wid >> 1;
    const int g = lane >> 2, t = lane & 3;

    float acc[4][8][4];
    gemm_tf32_mainloop_pipe(smu, g_xt + (size_t)(by * 128) * CC, CC,
                            g_wqt + bx * 128, 3 * CC, acc);

    const int g3 = bx >> 3;
    uint32_t* dstbase = (g3 == 0) ? g_q : (g3 == 1) ? g_k : g_v;

    #pragma unroll
    for (int mi = 0; mi < 4; mi++) {
        #pragma unroll
        for (int rr = 0; rr < 2; rr++) {
            int m = by * 128 + warp_m * 64 + mi * 16 + g + rr * 8;
            int b = m >> 11, tloc = m & (TT - 1);
            #pragma unroll
            for (int ni = 0; ni < 8; ni++) {
                int n = bx * 128 + warp_n * 64 + ni * 8 + 2 * t;
                int rem = n & 1023;
                int h = rem >> 6, d = rem & 63;
                uint2 v2 = make_uint2(f2tf32(acc[mi][ni][rr * 2]),
                                      f2tf32(acc[mi][ni][rr * 2 + 1]));
                *(uint2*)&dstbase[(((size_t)(b * HH + h)) * TT + tloc) * DD + d] = v2;
            }
        }
    }
}

// ---------------------------------------------------------------------------
// Kernel 3: out = y @ w_proj + b_proj (y, w already tf32 bits)
// ---------------------------------------------------------------------------
__global__ __launch_bounds__(128, 2) void proj_mma_kernel(
    const float* __restrict__ bias, float* __restrict__ out)
{
    extern __shared__ uint32_t smu[];
    const int bx = blockIdx.x;
    const int by = blockIdx.y;
    const int tid = threadIdx.x;
    const int wid = tid >> 5, lane = tid & 31;
    const int warp_m = wid & 1, warp_n = wid >> 1;
    const int g = lane >> 2, t = lane & 3;

    float acc[4][8][4];
    gemm_tf32_mainloop_pipe(smu, g_y + (size_t)(by * 128) * CC, CC,
                            g_wpt + bx * 128, CC, acc);

    #pragma unroll
    for (int mi = 0; mi < 4; mi++) {
        #pragma unroll
        for (int rr = 0; rr < 2; rr++) {
            int m = by * 128 + warp_m * 64 + mi * 16 + g + rr * 8;
            #pragma unroll
            for (int ni = 0; ni < 8; ni++) {
                int n = bx * 128 + warp_n * 64 + ni * 8 + 2 * t;
                float2 v2;
                v2.x = acc[mi][ni][rr * 2]     + bias[n];
                v2.y = acc[mi][ni][rr * 2 + 1] + bias[n + 1];
                *(float2*)&out[(size_t)m * CC + n] = v2;
            }
        }
    }
}

// ===========================================================================
// Flash attention, tf32 mma, 2-stage pipelined K/V.
// CTA: 128 query rows of one (b,h). 8 warps x 16 rows. Key tiles of 64.
// Stage: Ks [64 d][64 key] XOR-swizzled + Vs [64 key][72 d]. Ps [128][72].
// ===========================================================================
#define QTILE 128
#define KTILE 64
#define SP 72
#define ST_U32 (64*64 + 64*SP)                 // 8704 per stage
#define FA_SMEM_U32 (2*ST_U32 + 128*SP)        // 26624
#define FA_SMEM_BYTES (FA_SMEM_U32 * 4)        // 106496

__global__ __launch_bounds__(256) void flash_attn_mma_kernel()
{
    extern __shared__ uint32_t smu[];
    uint32_t* Ps = smu + 2 * ST_U32;

    const int qi = (int)gridDim.x - 1 - (int)blockIdx.x;   // heavy CTAs first
    const int bh = blockIdx.y;
    const int b = bh >> 4, h = bh & 15;
    const int tid = threadIdx.x;
    const int wid = tid >> 5, lane = tid & 31;
    const int g = lane >> 2, t = lane & 3;
    const int wbase = wid * 16;

    // ---- stage Q into Ps ----
    const uint32_t* qptr = g_q + ((size_t)bh * TT + qi * QTILE) * DD;
    #pragma unroll
    for (int u = 0; u < 8; u++) {
        int f = u * 256 + tid;
        int row = f >> 4, c4 = (f & 15) * 4;
        uint4 v = ((const uint4*)qptr)[f];
        uint32_t* p = &Ps[row * SP + c4];
        p[0] = v.x; p[1] = v.y; p[2] = v.z; p[3] = v.w;
    }

    // ---- prologue: load + store K/V tile 0 into stage 0 ----
    const int nkt = 2 * qi + 2;
    uint4 rk[4], rv[4];
    {
        const uint32_t* kp = g_k + ((size_t)bh * TT) * DD;
        const uint32_t* vp = g_v + ((size_t)bh * TT) * DD;
        #pragma unroll
        for (int u = 0; u < 4; u++) {
            int f = u * 256 + tid;
            rk[u] = *(const uint4*)(kp + (size_t)(f & 63) * DD + ((f >> 6) * 4));
            rv[u] = *(const uint4*)(vp + (size_t)(f >> 4) * DD + ((f & 15) * 4));
        }
        uint32_t* Ks0 = smu;
        uint32_t* Vs0 = smu + 64 * 64;
        #pragma unroll
        for (int u = 0; u < 4; u++) {
            int f = u * 256 + tid;
            int key = f & 63, c4 = (f >> 6) * 4;
            Ks0[(c4 + 0) * 64 + (key ^ (((c4 + 0) & 3) * 8))] = rk[u].x;
            Ks0[(c4 + 1) * 64 + (key ^ (((c4 + 1) & 3) * 8))] = rk[u].y;
            Ks0[(c4 + 2) * 64 + (key ^ (((c4 + 2) & 3) * 8))] = rk[u].z;
            Ks0[(c4 + 3) * 64 + (key ^ (((c4 + 3) & 3) * 8))] = rk[u].w;
            int row = f >> 4, vc4 = (f & 15) * 4;
            uint32_t* p = &Vs0[row * SP + vc4];
            p[0] = rv[u].x; p[1] = rv[u].y; p[2] = rv[u].z; p[3] = rv[u].w;
        }
    }
    __syncthreads();

    // ---- Q fragments (warp-local rows of Ps) ----
    uint32_t qf[8][4];
    #pragma unroll
    for (int ks = 0; ks < 8; ks++) {
        qf[ks][0] = Ps[(wbase + g) * SP + ks * 8 + t];
        qf[ks][1] = Ps[(wbase + g + 8) * SP + ks * 8 + t];
        qf[ks][2] = Ps[(wbase + g) * SP + ks * 8 + t + 4];
        qf[ks][3] = Ps[(wbase + g + 8) * SP + ks * 8 + t + 4];
    }

    float of[8][4];
    #pragma unroll
    for (int nf = 0; nf < 8; nf++)
        #pragma unroll
        for (int r = 0; r < 4; r++) of[nf][r] = 0.f;
    float m0 = -1e30f, m1 = -1e30f, l0 = 0.f, l1 = 0.f;

    const int qrow0 = qi * QTILE + wbase + g;
    const int qrow1 = qrow0 + 8;

    for (int kt = 0; kt < nkt; kt++) {
        uint32_t* Ksc = smu + (kt & 1) * ST_U32;
        uint32_t* Vsc = Ksc + 64 * 64;

        // prefetch next tile
        const bool more = (kt + 1 < nkt);
        if (more) {
            const uint32_t* kp = g_k + ((size_t)bh * TT + (kt + 1) * KTILE) * DD;
            const uint32_t* vp = g_v + ((size_t)bh * TT + (kt + 1) * KTILE) * DD;
            #pragma unroll
            for (int u = 0; u < 4; u++) {
                int f = u * 256 + tid;
                rk[u] = *(const uint4*)(kp + (size_t)(f & 63) * DD + ((f >> 6) * 4));
                rv[u] = *(const uint4*)(vp + (size_t)(f >> 4) * DD + ((f & 15) * 4));
            }
        }

        // ---- S = Q @ K^T ----
        float sf[8][4];
        #pragma unroll
        for (int nf = 0; nf < 8; nf++)
            #pragma unroll
            for (int r = 0; r < 4; r++) sf[nf][r] = 0.f;

        #pragma unroll
        for (int ks = 0; ks < 8; ks++) {
            const int r0 = (8 * ks + t) * 64;
            const int r1 = (8 * ks + t + 4) * 64;
            #pragma unroll
            for (int nf = 0; nf < 8; nf++) {
                const int keyx = (nf * 8 + g) ^ (8 * t);
                uint32_t bf[2] = { Ksc[r0 + keyx], Ksc[r1 + keyx] };
                mma_tf32_16x8x8(sf[nf], qf[ks], bf);
            }
        }

        // ---- scale + causal mask ----
        const bool need_mask = (kt >= 2 * qi);
        #pragma unroll
        for (int nf = 0; nf < 8; nf++) {
            int kc0 = kt * KTILE + nf * 8 + 2 * t;
            int kc1 = kc0 + 1;
            if (need_mask) {
                sf[nf][0] = (kc0 <= qrow0) ? sf[nf][0] * SCALE : -1e30f;
                sf[nf][1] = (kc1 <= qrow0) ? sf[nf][1] * SCALE : -1e30f;
                sf[nf][2] = (kc0 <= qrow1) ? sf[nf][2] * SCALE : -1e30f;
                sf[nf][3] = (kc1 <= qrow1) ? sf[nf][3] * SCALE : -1e30f;
            } else {
                sf[nf][0] *= SCALE; sf[nf][1] *= SCALE;
                sf[nf][2] *= SCALE; sf[nf][3] *= SCALE;
            }
        }

        // ---- online softmax ----
        float mx0 = -1e30f, mx1 = -1e30f;
        #pragma unroll
        for (int nf = 0; nf < 8; nf++) {
            mx0 = fmaxf(mx0, fmaxf(sf[nf][0], sf[nf][1]));
            mx1 = fmaxf(mx1, fmaxf(sf[nf][2], sf[nf][3]));
        }
        #pragma unroll
        for (int off = 1; off < 4; off <<= 1) {
            mx0 = fmaxf(mx0, __shfl_xor_sync(0xffffffffu, mx0, off));
            mx1 = fmaxf(mx1, __shfl_xor_sync(0xffffffffu, mx1, off));
        }
        float mn0 = fmaxf(m0, mx0), mn1 = fmaxf(m1, mx1);
        float a0 = __expf(m0 - mn0), a1 = __expf(m1 - mn1);
        m0 = mn0; m1 = mn1;

        float s0 = 0.f, s1 = 0.f;
        #pragma unroll
        for (int nf = 0; nf < 8; nf++) {
            sf[nf][0] = __expf(sf[nf][0] - mn0);
            sf[nf][1] = __expf(sf[nf][1] - mn0);
            sf[nf][2] = __expf(sf[nf][2] - mn1);
            sf[nf][3] = __expf(sf[nf][3] - mn1);
            s0 += sf[nf][0] + sf[nf][1];
            s1 += sf[nf][2] + sf[nf][3];
        }
        #pragma unroll
        for (int off = 1; off < 4; off <<= 1) {
            s0 += __shfl_xor_sync(0xffffffffu, s0, off);
            s1 += __shfl_xor_sync(0xffffffffu, s1, off);
        }
        l0 = l0 * a0 + s0;
        l1 = l1 * a1 + s1;

        // ---- store next K/V into the other stage (freed at sync of kt-1) ----
        if (more) {
            uint32_t* Ksn = smu + ((kt + 1) & 1) * ST_U32;
            uint32_t* Vsn = Ksn + 64 * 64;
            #pragma unroll
            for (int u = 0; u < 4; u++) {
                int f = u * 256 + tid;
                int key = f & 63, c4 = (f >> 6) * 4;
                Ksn[(c4 + 0) * 64 + (key ^ (((c4 + 0) & 3) * 8))] = rk[u].x;
                Ksn[(c4 + 1) * 64 + (key ^ (((c4 + 1) & 3) * 8))] = rk[u].y;
                Ksn[(c4 + 2) * 64 + (key ^ (((c4 + 2) & 3) * 8))] = rk[u].z;
                Ksn[(c4 + 3) * 64 + (key ^ (((c4 + 3) & 3) * 8))] = rk[u].w;
                int row = f >> 4, vc4 = (f & 15) * 4;
                uint32_t* p = &Vsn[row * SP + vc4];
                p[0] = rv[u].x; p[1] = rv[u].y; p[2] = rv[u].z; p[3] = rv[u].w;
            }
        }

        // ---- rescale O ----
        #pragma unroll
        for (int nf = 0; nf < 8; nf++) {
            of[nf][0] *= a0; of[nf][1] *= a0;
            of[nf][2] *= a1; of[nf][3] *= a1;
        }

        // ---- P to smem (warp-local) then O += P @ V ----
        __syncwarp();
        #pragma unroll
        for (int nf = 0; nf < 8; nf++) {
            uint2 p01 = make_uint2(f2tf32(sf[nf][0]), f2tf32(sf[nf][1]));
            uint2 p23 = make_uint2(f2tf32(sf[nf][2]), f2tf32(sf[nf][3]));
            *(uint2*)&Ps[(wbase + g) * SP + nf * 8 + 2 * t]     = p01;
            *(uint2*)&Ps[(wbase + g + 8) * SP + nf * 8 + 2 * t] = p23;
        }
        __syncwarp();

        #pragma unroll
        for (int ks = 0; ks < 8; ks++) {
            uint32_t af[4];
            af[0] = Ps[(wbase + g) * SP + ks * 8 + t];
            af[1] = Ps[(wbase + g + 8) * SP + ks * 8 + t];
            af[2] = Ps[(wbase + g) * SP + ks * 8 + t + 4];
            af[3] = Ps[(wbase + g + 8) * SP + ks * 8 + t + 4];
            const int r0 = (8 * ks + t) * SP;
            const int r1 = (8 * ks + t + 4) * SP;
            #pragma unroll
            for (int nf = 0; nf < 8; nf++) {
                uint32_t bf[2] = { Vsc[r0 + nf * 8 + g], Vsc[r1 + nf * 8 + g] };
                mma_tf32_16x8x8(of[nf], af, bf);
            }
        }
        __syncthreads();
    }

    // ---- epilogue: normalize, convert to tf32 bits, write g_y ----
    float inv0 = 1.f / l0, inv1 = 1.f / l1;
    const int t0 = qi * QTILE + wbase + g;
    const int t1 = t0 + 8;
    uint32_t* y0 = g_y + ((size_t)b * TT + t0) * CC + h * DD;
    uint32_t* y1 = g_y + ((size_t)b * TT + t1) * CC + h * DD;
    #pragma unroll
    for (int nf = 0; nf < 8; nf++) {
        int d = nf * 8 + 2 * t;
        *(uint2*)&y0[d] = make_uint2(f2tf32(of[nf][0] * inv0), f2tf32(of[nf][1] * inv0));
        *(uint2*)&y1[d] = make_uint2(f2tf32(of[nf][2] * inv1), f2tf32(of[nf][3] * inv1));
    }
}

// ---------------------------------------------------------------------------
extern "C" void kernel_launch(void* const* d_in, const int* in_sizes, int n_in,
                              void* d_out, int out_size)
{
    const float* x      = (const float*)d_in[0];
    const float* w_qkv  = (const float*)d_in[1];
    const float* w_proj = (const float*)d_in[2];
    const float* b_proj = (const float*)d_in[3];
    float* out = (float*)d_out;

    static bool attr_set = false;
    if (!attr_set) {
        cudaFuncSetAttribute(flash_attn_mma_kernel,
                             cudaFuncAttributeMaxDynamicSharedMemorySize,
                             FA_SMEM_BYTES);
        cudaFuncSetAttribute(qkv_mma_kernel,
                             cudaFuncAttributeMaxDynamicSharedMemorySize,
                             GEMM_SMEM_BYTES);
        cudaFuncSetAttribute(proj_mma_kernel,
                             cudaFuncAttributeMaxDynamicSharedMemorySize,
                             GEMM_SMEM_BYTES);
        attr_set = true;
    }

    uint32_t* xt; cudaGetSymbolAddress((void**)&xt, g_xt);
    uint32_t* wqt; cudaGetSymbolAddress((void**)&wqt, g_wqt);
    uint32_t* wpt; cudaGetSymbolAddress((void**)&wpt, g_wpt);

    // 0) bulk tf32 conversion of inputs
    conv_tf32_kernel<<<1184, 256>>>((const float4*)x, (uint4*)xt, MROWS * CC / 4);
    conv_tf32_kernel<<<1184, 256>>>((const float4*)w_qkv, (uint4*)wqt, CC * 3 * CC / 4);
    conv_tf32_kernel<<<1184, 256>>>((const float4*)w_proj, (uint4*)wpt, CC * CC / 4);

    // 1) QKV projection + scatter
    {
        dim3 grid(3*CC/128, MROWS/128);   // (24, 32)
        qkv_mma_kernel<<<grid, 128, GEMM_SMEM_BYTES>>>();
    }
    // 2) flash attention
    {
        dim3 grid(TT/QTILE, BB*HH);       // (16, 32)
        flash_attn_mma_kernel<<<grid, 256, FA_SMEM_BYTES>>>();
    }
    // 3) output projection + bias
    {
        dim3 grid(CC/128, MROWS/128);     // (8, 32)
        proj_mma_kernel<<<grid, 128, GEMM_SMEM_BYTES>>>(b_proj, out);
    }
}

// round 11
// speedup vs baseline: 4.5595x; 1.3894x over previous
#include <cuda_runtime.h>
#include <cuda_fp16.h>
#include <cstdint>

// Problem constants
#define BB   2
#define TT   2048
#define CC   1024
#define HH   16
#define DD   64
#define MROWS (BB*TT)          // 4096
#define SCALE 0.125f           // 1/sqrt(64)

// Scratch (device globals). fp16 data stored as packed u32 (half2 pairs).
__device__ uint32_t g_xh [MROWS*CC/2];     // x fp16 [M][C]
__device__ uint32_t g_wqh[3*CC*CC/2];      // w_qkv^T fp16 [3C][C]  ([n][k])
__device__ uint32_t g_wph[CC*CC/2];        // w_proj^T fp16 [C][C]
__device__ uint32_t g_q  [BB*HH*TT*DD/2];  // [bh][t][d] fp16
__device__ uint32_t g_k  [BB*HH*TT*DD/2];  // [bh][t][d] fp16
__device__ uint32_t g_vt [BB*HH*DD*TT/2];  // V^T: [bh][d][t] fp16
__device__ uint32_t g_yh [MROWS*CC/2];     // attention out fp16 [M][C]

// ===========================================================================
// helpers
// ===========================================================================
__device__ __forceinline__ uint32_t pack_half2(float lo, float hi) {
    uint32_t u;
    asm("cvt.rn.f16x2.f32 %0, %1, %2;" : "=r"(u) : "f"(hi), "f"(lo));
    return u;
}

__device__ __forceinline__ void mma_f16_16x8x16(float* c, const uint32_t* a,
                                                const uint32_t* b) {
    asm volatile(
        "mma.sync.aligned.m16n8k16.row.col.f32.f16.f16.f32 "
        "{%0,%1,%2,%3}, {%4,%5,%6,%7}, {%8,%9}, {%0,%1,%2,%3};\n"
        : "+f"(c[0]), "+f"(c[1]), "+f"(c[2]), "+f"(c[3])
        : "r"(a[0]), "r"(a[1]), "r"(a[2]), "r"(a[3]),
          "r"(b[0]), "r"(b[1]));
}

// ---------------------------------------------------------------------------
// Kernel 0a: fp32 -> fp16 bulk convert (row-major preserved)
// ---------------------------------------------------------------------------
__global__ __launch_bounds__(256) void conv_f16_kernel(
    const float4* __restrict__ in, uint2* __restrict__ out, int n4)
{
    int i = blockIdx.x * blockDim.x + threadIdx.x;
    int stride = gridDim.x * blockDim.x;
    for (; i < n4; i += stride) {
        float4 v = in[i];
        uint2 o;
        o.x = pack_half2(v.x, v.y);
        o.y = pack_half2(v.z, v.w);
        out[i] = o;
    }
}

// ---------------------------------------------------------------------------
// Kernel 0b: fp32 [K][N] -> fp16 [N][K] transpose (weights)
// ---------------------------------------------------------------------------
__global__ __launch_bounds__(256) void trans_f16_kernel(
    const float* __restrict__ in, uint32_t* __restrict__ out, int N, int K)
{
    __shared__ float ts[32][33];
    const int k0 = blockIdx.y * 32, n0 = blockIdx.x * 32;
    const int tx = threadIdx.x & 31, ty = threadIdx.x >> 5;
    #pragma unroll
    for (int j = 0; j < 4; j++)
        ts[ty + 8*j][tx] = in[(size_t)(k0 + ty + 8*j) * N + n0 + tx];
    __syncthreads();
    const int n = threadIdx.x >> 3, c = threadIdx.x & 7;
    out[(size_t)(n0 + n) * (K >> 1) + (k0 >> 1) + c] =
        pack_half2(ts[2*c][n], ts[2*c + 1][n]);
    out[(size_t)(n0 + n) * (K >> 1) + (k0 >> 1) + c + 8] =
        pack_half2(ts[2*c + 16][n], ts[2*c + 17][n]);
}

// ===========================================================================
// fp16 GEMM mainloop. CTA 128x128, 128 threads (4 warps), warp 64x64.
// K chunk 32 fp16 (16 u32). 2-stage double buffer, 1 sync/chunk.
// Smem row pitch 20 u32 -> fragment reads conflict-free.
// A fp16 [M][K] (u32 [M][512]); B fp16 [N][K] (u32 [N][512]).
// ===========================================================================
#define GP 20
#define GST (128*GP*2)                   // stage u32 (A + B)
#define GEMM_SMEM_BYTES (2 * GST * 4)    // 40960 B

__device__ __forceinline__ void gemm_f16_mainloop(
    uint32_t* sm, const uint32_t* __restrict__ A,
    const uint32_t* __restrict__ B, float acc[4][8][4])
{
    const int tid = threadIdx.x;
    const int wid = tid >> 5, lane = tid & 31;
    const int warp_m = wid & 1, warp_n = wid >> 1;
    const int g = lane >> 2, t = lane & 3;

    #pragma unroll
    for (int mi = 0; mi < 4; mi++)
        #pragma unroll
        for (int ni = 0; ni < 8; ni++)
            #pragma unroll
            for (int r = 0; r < 4; r++) acc[mi][ni][r] = 0.f;

    const uint32_t* Ar = A + (size_t)tid * (CC/2);
    const uint32_t* Br = B + (size_t)tid * (CC/2);

    uint4 ra[4], rb[4];
    #pragma unroll
    for (int u = 0; u < 4; u++) {
        ra[u] = *(const uint4*)(Ar + u * 4);
        rb[u] = *(const uint4*)(Br + u * 4);
    }
    {
        uint32_t* As = sm;
        uint32_t* Bs = sm + 128 * GP;
        #pragma unroll
        for (int u = 0; u < 4; u++) {
            *(uint4*)&As[tid * GP + u * 4] = ra[u];
            *(uint4*)&Bs[tid * GP + u * 4] = rb[u];
        }
    }
    __syncthreads();

    for (int c = 0; c < CC / 32; c++) {
        if (c < CC / 32 - 1) {
            #pragma unroll
            for (int u = 0; u < 4; u++) {
                ra[u] = *(const uint4*)(Ar + (c + 1) * 16 + u * 4);
                rb[u] = *(const uint4*)(Br + (c + 1) * 16 + u * 4);
            }
        }

        uint32_t* As = sm + (c & 1) * GST;
        uint32_t* Bs = As + 128 * GP;
        #pragma unroll
        for (int ks = 0; ks < 2; ks++) {
            const int k8 = ks * 8;
            uint32_t af[4][4];
            #pragma unroll
            for (int mi = 0; mi < 4; mi++) {
                int mb = warp_m * 64 + mi * 16;
                af[mi][0] = As[(mb + g) * GP + k8 + t];
                af[mi][1] = As[(mb + g + 8) * GP + k8 + t];
                af[mi][2] = As[(mb + g) * GP + k8 + t + 4];
                af[mi][3] = As[(mb + g + 8) * GP + k8 + t + 4];
            }
            uint32_t bf[8][2];
            #pragma unroll
            for (int ni = 0; ni < 8; ni++) {
                int nb = warp_n * 64 + ni * 8;
                bf[ni][0] = Bs[(nb + g) * GP + k8 + t];
                bf[ni][1] = Bs[(nb + g) * GP + k8 + t + 4];
            }
            #pragma unroll
            for (int mi = 0; mi < 4; mi++)
                #pragma unroll
                for (int ni = 0; ni < 8; ni++)
                    mma_f16_16x8x16(acc[mi][ni], af[mi], bf[ni]);
        }

        if (c < CC / 32 - 1) {
            uint32_t* As2 = sm + ((c + 1) & 1) * GST;
            uint32_t* Bs2 = As2 + 128 * GP;
            #pragma unroll
            for (int u = 0; u < 4; u++) {
                *(uint4*)&As2[tid * GP + u * 4] = ra[u];
                *(uint4*)&Bs2[tid * GP + u * 4] = rb[u];
            }
        }
        __syncthreads();
    }
}

// ---------------------------------------------------------------------------
// Kernel 1: QKV projection. q,k -> [bh][t][d] fp16; v -> V^T [bh][d][t] fp16.
// grid (24, 32), block 128
// ---------------------------------------------------------------------------
__global__ __launch_bounds__(128, 2) void qkv_mma_kernel()
{
    extern __shared__ uint32_t smu[];
    const int bx = blockIdx.x;   // 0..23
    const int by = blockIdx.y;   // 0..31
    const int tid = threadIdx.x;
    const int wid = tid >> 5, lane = tid & 31;
    const int warp_m = wid & 1, warp_n = wid >> 1;
    const int g = lane >> 2, t = lane & 3;

    float acc[4][8][4];
    gemm_f16_mainloop(smu, g_xh + (size_t)(by * 128) * (CC/2),
                      g_wqh + (size_t)(bx * 128) * (CC/2), acc);

    const int g3 = bx >> 3;   // 0=q 1=k 2=v
    if (g3 < 2) {
        uint32_t* dstbase = (g3 == 0) ? g_q : g_k;
        #pragma unroll
        for (int mi = 0; mi < 4; mi++) {
            #pragma unroll
            for (int rr = 0; rr < 2; rr++) {
                int m = by * 128 + warp_m * 64 + mi * 16 + g + rr * 8;
                int b = m >> 11, tloc = m & (TT - 1);
                #pragma unroll
                for (int ni = 0; ni < 8; ni++) {
                    int n = bx * 128 + warp_n * 64 + ni * 8 + 2 * t;
                    int rem = n & 1023;
                    int h = rem >> 6, d = rem & 63;   // d even
                    dstbase[(((size_t)(b * HH + h)) * TT + tloc) * (DD/2) + (d >> 1)] =
                        pack_half2(acc[mi][ni][rr * 2], acc[mi][ni][rr * 2 + 1]);
                }
            }
        }
    } else {
        // V: write transposed fp16 scalars into g_vt [bh][d][t]
        unsigned short* vt = (unsigned short*)g_vt;
        #pragma unroll
        for (int mi = 0; mi < 4; mi++) {
            #pragma unroll
            for (int rr = 0; rr < 2; rr++) {
                int m = by * 128 + warp_m * 64 + mi * 16 + g + rr * 8;
                int b = m >> 11, tloc = m & (TT - 1);
                #pragma unroll
                for (int ni = 0; ni < 8; ni++) {
                    int n = bx * 128 + warp_n * 64 + ni * 8 + 2 * t;
                    int rem = n & 1023;
                    int h = rem >> 6, d = rem & 63;
                    size_t base = ((size_t)(b * HH + h) * DD + d) * TT + tloc;
                    vt[base]      = __half_as_ushort(__float2half_rn(acc[mi][ni][rr * 2]));
                    vt[base + TT] = __half_as_ushort(__float2half_rn(acc[mi][ni][rr * 2 + 1]));
                }
            }
        }
    }
}

// ---------------------------------------------------------------------------
// Kernel 3: out = y @ w_proj + b_proj (fp32 out)
// grid (8, 32), block 128
// ---------------------------------------------------------------------------
__global__ __launch_bounds__(128, 2) void proj_mma_kernel(
    const float* __restrict__ bias, float* __restrict__ out)
{
    extern __shared__ uint32_t smu[];
    const int bx = blockIdx.x;
    const int by = blockIdx.y;
    const int tid = threadIdx.x;
    const int wid = tid >> 5, lane = tid & 31;
    const int warp_m = wid & 1, warp_n = wid >> 1;
    const int g = lane >> 2, t = lane & 3;

    float acc[4][8][4];
    gemm_f16_mainloop(smu, g_yh + (size_t)(by * 128) * (CC/2),
                      g_wph + (size_t)(bx * 128) * (CC/2), acc);

    #pragma unroll
    for (int mi = 0; mi < 4; mi++) {
        #pragma unroll
        for (int rr = 0; rr < 2; rr++) {
            int m = by * 128 + warp_m * 64 + mi * 16 + g + rr * 8;
            #pragma unroll
            for (int ni = 0; ni < 8; ni++) {
                int n = bx * 128 + warp_n * 64 + ni * 8 + 2 * t;
                float2 v2;
                v2.x = acc[mi][ni][rr * 2]     + bias[n];
                v2.y = acc[mi][ni][rr * 2 + 1] + bias[n + 1];
                *(float2*)&out[(size_t)m * CC + n] = v2;
            }
        }
    }
}

// ===========================================================================
// Flash attention, fp16 mma (fp32 softmax/accum).
// CTA: 128 q-rows of one (b,h), 256 threads, 8 warps x 16 rows. KTILE 64.
// Smem per stage: Kh [64 key][32 d2 (pitch 36)] + Vh [64 d][32 t2 (pitch 36)].
// Tile = 64 rows x 32 u32 = 512 uint4 -> each of 256 threads moves TWO uint4.
// Q fragments loaded directly from gmem. P stays in registers (fp16 a-frags).
// ===========================================================================
#define ATP 36
#define AST (64*ATP*2)                    // stage u32 = 4608
#define FA_SMEM_BYTES (2 * AST * 4)       // 36864

__global__ __launch_bounds__(256, 2) void flash_attn_f16_kernel()
{
    extern __shared__ uint32_t smu[];

    const int qi = (int)gridDim.x - 1 - (int)blockIdx.x;   // heavy CTAs first
    const int bh = blockIdx.y;
    const int b = bh >> 4, h = bh & 15;
    const int tid = threadIdx.x;
    const int wid = tid >> 5, lane = tid & 31;
    const int g = lane >> 2, t = lane & 3;
    const int wbase = wid * 16;

    // ---- Q fragments straight from gmem ----
    const uint32_t* q0 = g_q + ((size_t)bh * TT + qi * 128 + wbase + g) * (DD/2);
    const uint32_t* q1 = q0 + 8 * (DD/2);
    uint32_t qf[4][4];
    #pragma unroll
    for (int ks = 0; ks < 4; ks++) {
        qf[ks][0] = q0[ks * 8 + t];
        qf[ks][1] = q1[ks * 8 + t];
        qf[ks][2] = q0[ks * 8 + t + 4];
        qf[ks][3] = q1[ks * 8 + t + 4];
    }

    const int nkt = 2 * qi + 2;
    const int krow = tid >> 2, u = tid & 3;     // K: key row / V: d row

    // ---- prologue: FULL tile 0 -> stage 0 (two uint4 per thread) ----
    uint4 rk[2], rv[2];
    {
        const uint32_t* kp = g_k + ((size_t)bh * TT + krow) * (DD/2);
        const uint32_t* vp = g_vt + ((size_t)bh * DD + krow) * (TT/2);
        rk[0] = *(const uint4*)(kp + u * 4);
        rk[1] = *(const uint4*)(kp + u * 4 + 16);
        rv[0] = *(const uint4*)(vp + u * 4);
        rv[1] = *(const uint4*)(vp + u * 4 + 16);
        uint32_t* Kh = smu;
        uint32_t* Vh = smu + 64 * ATP;
        *(uint4*)&Kh[krow * ATP + u * 4]      = rk[0];
        *(uint4*)&Kh[krow * ATP + u * 4 + 16] = rk[1];
        *(uint4*)&Vh[krow * ATP + u * 4]      = rv[0];
        *(uint4*)&Vh[krow * ATP + u * 4 + 16] = rv[1];
    }
    __syncthreads();

    float of[8][4];
    #pragma unroll
    for (int nf = 0; nf < 8; nf++)
        #pragma unroll
        for (int r = 0; r < 4; r++) of[nf][r] = 0.f;
    float m0 = -1e30f, m1 = -1e30f, l0 = 0.f, l1 = 0.f;

    const int qrow0 = qi * 128 + wbase + g;
    const int qrow1 = qrow0 + 8;

    for (int kt = 0; kt < nkt; kt++) {
        uint32_t* Ksc = smu + (kt & 1) * AST;
        uint32_t* Vsc = Ksc + 64 * ATP;
        const bool more = (kt + 1 < nkt);

        if (more) {
            const uint32_t* kp = g_k + ((size_t)bh * TT + (kt + 1) * 64 + krow) * (DD/2);
            const uint32_t* vp = g_vt + ((size_t)bh * DD + krow) * (TT/2) + (kt + 1) * 32;
            rk[0] = *(const uint4*)(kp + u * 4);
            rk[1] = *(const uint4*)(kp + u * 4 + 16);
            rv[0] = *(const uint4*)(vp + u * 4);
            rv[1] = *(const uint4*)(vp + u * 4 + 16);
        }

        // ---- S = Q @ K^T (fp16, k16 x4) ----
        float sf[8][4];
        #pragma unroll
        for (int nf = 0; nf < 8; nf++)
            #pragma unroll
            for (int r = 0; r < 4; r++) sf[nf][r] = 0.f;

        #pragma unroll
        for (int ks = 0; ks < 4; ks++) {
            #pragma unroll
            for (int nf = 0; nf < 8; nf++) {
                uint32_t bfr[2];
                bfr[0] = Ksc[(nf * 8 + g) * ATP + ks * 8 + t];
                bfr[1] = Ksc[(nf * 8 + g) * ATP + ks * 8 + t + 4];
                mma_f16_16x8x16(sf[nf], qf[ks], bfr);
            }
        }

        // ---- scale + causal mask ----
        const bool need_mask = (kt >= 2 * qi);
        #pragma unroll
        for (int nf = 0; nf < 8; nf++) {
            int kc0 = kt * 64 + nf * 8 + 2 * t;
            int kc1 = kc0 + 1;
            if (need_mask) {
                sf[nf][0] = (kc0 <= qrow0) ? sf[nf][0] * SCALE : -1e30f;
                sf[nf][1] = (kc1 <= qrow0) ? sf[nf][1] * SCALE : -1e30f;
                sf[nf][2] = (kc0 <= qrow1) ? sf[nf][2] * SCALE : -1e30f;
                sf[nf][3] = (kc1 <= qrow1) ? sf[nf][3] * SCALE : -1e30f;
            } else {
                sf[nf][0] *= SCALE; sf[nf][1] *= SCALE;
                sf[nf][2] *= SCALE; sf[nf][3] *= SCALE;
            }
        }

        // ---- online softmax ----
        float mx0 = -1e30f, mx1 = -1e30f;
        #pragma unroll
        for (int nf = 0; nf < 8; nf++) {
            mx0 = fmaxf(mx0, fmaxf(sf[nf][0], sf[nf][1]));
            mx1 = fmaxf(mx1, fmaxf(sf[nf][2], sf[nf][3]));
        }
        #pragma unroll
        for (int off = 1; off < 4; off <<= 1) {
            mx0 = fmaxf(mx0, __shfl_xor_sync(0xffffffffu, mx0, off));
            mx1 = fmaxf(mx1, __shfl_xor_sync(0xffffffffu, mx1, off));
        }
        float mn0 = fmaxf(m0, mx0), mn1 = fmaxf(m1, mx1);
        float a0 = __expf(m0 - mn0), a1 = __expf(m1 - mn1);
        m0 = mn0; m1 = mn1;

        float s0 = 0.f, s1 = 0.f;
        #pragma unroll
        for (int nf = 0; nf < 8; nf++) {
            sf[nf][0] = __expf(sf[nf][0] - mn0);
            sf[nf][1] = __expf(sf[nf][1] - mn0);
            sf[nf][2] = __expf(sf[nf][2] - mn1);
            sf[nf][3] = __expf(sf[nf][3] - mn1);
            s0 += sf[nf][0] + sf[nf][1];
            s1 += sf[nf][2] + sf[nf][3];
        }
        #pragma unroll
        for (int off = 1; off < 4; off <<= 1) {
            s0 += __shfl_xor_sync(0xffffffffu, s0, off);
            s1 += __shfl_xor_sync(0xffffffffu, s1, off);
        }
        l0 = l0 * a0 + s0;
        l1 = l1 * a1 + s1;

        // ---- P -> fp16 a-frags (registers only) ----
        uint32_t pf[4][4];
        #pragma unroll
        for (int ks = 0; ks < 4; ks++) {
            pf[ks][0] = pack_half2(sf[2*ks][0],     sf[2*ks][1]);
            pf[ks][1] = pack_half2(sf[2*ks][2],     sf[2*ks][3]);
            pf[ks][2] = pack_half2(sf[2*ks + 1][0], sf[2*ks + 1][1]);
            pf[ks][3] = pack_half2(sf[2*ks + 1][2], sf[2*ks + 1][3]);
        }

        // ---- store next K/V into the other stage (full tile) ----
        if (more) {
            uint32_t* Ksn = smu + ((kt + 1) & 1) * AST;
            uint32_t* Vsn = Ksn + 64 * ATP;
            *(uint4*)&Ksn[krow * ATP + u * 4]      = rk[0];
            *(uint4*)&Ksn[krow * ATP + u * 4 + 16] = rk[1];
            *(uint4*)&Vsn[krow * ATP + u * 4]      = rv[0];
            *(uint4*)&Vsn[krow * ATP + u * 4 + 16] = rv[1];
        }

        // ---- rescale O, then O += P @ V ----
        #pragma unroll
        for (int nf = 0; nf < 8; nf++) {
            of[nf][0] *= a0; of[nf][1] *= a0;
            of[nf][2] *= a1; of[nf][3] *= a1;
        }
        #pragma unroll
        for (int ks = 0; ks < 4; ks++) {
            #pragma unroll
            for (int nf = 0; nf < 8; nf++) {
                uint32_t bfr[2];
                bfr[0] = Vsc[(nf * 8 + g) * ATP + ks * 8 + t];
                bfr[1] = Vsc[(nf * 8 + g) * ATP + ks * 8 + t + 4];
                mma_f16_16x8x16(of[nf], pf[ks], bfr);
            }
        }
        __syncthreads();
    }

    // ---- epilogue: normalize -> fp16 -> g_yh ----
    float inv0 = 1.f / l0, inv1 = 1.f / l1;
    const int t0 = qi * 128 + wbase + g;
    const int t1 = t0 + 8;
    uint32_t* y0 = g_yh + ((size_t)b * TT + t0) * (CC/2) + h * (DD/2);
    uint32_t* y1 = g_yh + ((size_t)b * TT + t1) * (CC/2) + h * (DD/2);
    #pragma unroll
    for (int nf = 0; nf < 8; nf++) {
        int d2 = nf * 4 + t;
        y0[d2] = pack_half2(of[nf][0] * inv0, of[nf][1] * inv0);
        y1[d2] = pack_half2(of[nf][2] * inv1, of[nf][3] * inv1);
    }
}

// ---------------------------------------------------------------------------
extern "C" void kernel_launch(void* const* d_in, const int* in_sizes, int n_in,
                              void* d_out, int out_size)
{
    const float* x      = (const float*)d_in[0];
    const float* w_qkv  = (const float*)d_in[1];
    const float* w_proj = (const float*)d_in[2];
    const float* b_proj = (const float*)d_in[3];
    float* out = (float*)d_out;

    static bool attr_set = false;
    if (!attr_set) {
        cudaFuncSetAttribute(flash_attn_f16_kernel,
                             cudaFuncAttributeMaxDynamicSharedMemorySize,
                             FA_SMEM_BYTES);
        cudaFuncSetAttribute(qkv_mma_kernel,
                             cudaFuncAttributeMaxDynamicSharedMemorySize,
                             GEMM_SMEM_BYTES);
        cudaFuncSetAttribute(proj_mma_kernel,
                             cudaFuncAttributeMaxDynamicSharedMemorySize,
                             GEMM_SMEM_BYTES);
        attr_set = true;
    }

    uint32_t* xh;  cudaGetSymbolAddress((void**)&xh,  g_xh);
    uint32_t* wqh; cudaGetSymbolAddress((void**)&wqh, g_wqh);
    uint32_t* wph; cudaGetSymbolAddress((void**)&wph, g_wph);

    // 0) input conversion: x -> fp16 row-major; weights -> fp16 transposed
    conv_f16_kernel<<<1184, 256>>>((const float4*)x, (uint2*)xh, MROWS * CC / 4);
    {
        dim3 grid(3 * CC / 32, CC / 32);   // (96, 32)
        trans_f16_kernel<<<grid, 256>>>(w_qkv, wqh, 3 * CC, CC);
    }
    {
        dim3 grid(CC / 32, CC / 32);       // (32, 32)
        trans_f16_kernel<<<grid, 256>>>(w_proj, wph, CC, CC);
    }

    // 1) QKV projection + scatter (q,k row-major; v transposed)
    {
        dim3 grid(3 * CC / 128, MROWS / 128);   // (24, 32)
        qkv_mma_kernel<<<grid, 128, GEMM_SMEM_BYTES>>>();
    }
    // 2) flash attention
    {
        dim3 grid(TT / 128, BB * HH);           // (16, 32)
        flash_attn_f16_kernel<<<grid, 256, FA_SMEM_BYTES>>>();
    }
    // 3) output projection + bias
    {
        dim3 grid(CC / 128, MROWS / 128);       // (8, 32)
        proj_mma_kernel<<<grid, 128, GEMM_SMEM_BYTES>>>(b_proj, out);
    }
}

// round 12
// speedup vs baseline: 5.2362x; 1.1484x over previous
#include <cuda_runtime.h>
#include <cuda_fp16.h>
#include <cstdint>

// Problem constants
#define BB   2
#define TT   2048
#define CC   1024
#define HH   16
#define DD   64
#define MROWS (BB*TT)          // 4096
#define SCALE 0.125f           // 1/sqrt(64)

// Scratch (device globals). fp16 data stored as packed u32 (half2 pairs).
__device__ uint32_t g_xh [MROWS*CC/2];     // x fp16 [M][C]
__device__ uint32_t g_wqh[3*CC*CC/2];      // w_qkv^T fp16 [3C][C]  ([n][k])
__device__ uint32_t g_wph[CC*CC/2];        // w_proj^T fp16 [C][C]
__device__ uint32_t g_q  [BB*HH*TT*DD/2];  // [bh][t][d] fp16
__device__ uint32_t g_k  [BB*HH*TT*DD/2];  // [bh][t][d] fp16
__device__ uint32_t g_vt [BB*HH*DD*TT/2];  // V^T: [bh][d][t] fp16
__device__ uint32_t g_yh [MROWS*CC/2];     // attention out fp16 [M][C]

// ===========================================================================
// helpers
// ===========================================================================
__device__ __forceinline__ uint32_t pack_half2(float lo, float hi) {
    uint32_t u;
    asm("cvt.rn.f16x2.f32 %0, %1, %2;" : "=r"(u) : "f"(hi), "f"(lo));
    return u;
}

__device__ __forceinline__ void mma_f16_16x8x16(float* c, const uint32_t* a,
                                                const uint32_t* b) {
    asm volatile(
        "mma.sync.aligned.m16n8k16.row.col.f32.f16.f16.f32 "
        "{%0,%1,%2,%3}, {%4,%5,%6,%7}, {%8,%9}, {%0,%1,%2,%3};\n"
        : "+f"(c[0]), "+f"(c[1]), "+f"(c[2]), "+f"(c[3])
        : "r"(a[0]), "r"(a[1]), "r"(a[2]), "r"(a[3]),
          "r"(b[0]), "r"(b[1]));
}

__device__ __forceinline__ void cp_async16(uint32_t dst, const void* src) {
    asm volatile("cp.async.cg.shared.global [%0], [%1], 16;"
                 :: "r"(dst), "l"(src));
}
__device__ __forceinline__ void cp_commit() {
    asm volatile("cp.async.commit_group;" ::: "memory");
}
__device__ __forceinline__ void cp_wait2() {
    asm volatile("cp.async.wait_group 2;" ::: "memory");
}

// ---------------------------------------------------------------------------
// Kernel 0a: fp32 -> fp16 bulk convert (row-major preserved)
// ---------------------------------------------------------------------------
__global__ __launch_bounds__(256) void conv_f16_kernel(
    const float4* __restrict__ in, uint2* __restrict__ out, int n4)
{
    int i = blockIdx.x * blockDim.x + threadIdx.x;
    int stride = gridDim.x * blockDim.x;
    for (; i < n4; i += stride) {
        float4 v = in[i];
        uint2 o;
        o.x = pack_half2(v.x, v.y);
        o.y = pack_half2(v.z, v.w);
        out[i] = o;
    }
}

// ---------------------------------------------------------------------------
// Kernel 0b: fp32 [K][N] -> fp16 [N][K] transpose (weights)
// ---------------------------------------------------------------------------
__global__ __launch_bounds__(256) void trans_f16_kernel(
    const float* __restrict__ in, uint32_t* __restrict__ out, int N, int K)
{
    __shared__ float ts[32][33];
    const int k0 = blockIdx.y * 32, n0 = blockIdx.x * 32;
    const int tx = threadIdx.x & 31, ty = threadIdx.x >> 5;
    #pragma unroll
    for (int j = 0; j < 4; j++)
        ts[ty + 8*j][tx] = in[(size_t)(k0 + ty + 8*j) * N + n0 + tx];
    __syncthreads();
    const int n = threadIdx.x >> 3, c = threadIdx.x & 7;
    out[(size_t)(n0 + n) * (K >> 1) + (k0 >> 1) + c] =
        pack_half2(ts[2*c][n], ts[2*c + 1][n]);
    out[(size_t)(n0 + n) * (K >> 1) + (k0 >> 1) + c + 8] =
        pack_half2(ts[2*c + 16][n], ts[2*c + 17][n]);
}

// ===========================================================================
// fp16 GEMM mainloop, cp.async 4-stage pipeline.
// CTA 128x128, 128 threads (4 warps), warp 64x64. K chunk 32 fp16 (16 u32).
// Stage: A [128][GP] + B [128][GP], pitch 20 u32 (80B rows, 16B aligned).
// Each thread cp.asyncs 8x16B per stage (its own A row + B row chunk).
// ===========================================================================
#define GP 20
#define GSTA (128*GP)                    // A part u32 per stage
#define GST (2*GSTA)                     // stage u32 = 5120 (20480 B)
#define NSTAGE 4
#define GEMM_SMEM_BYTES (NSTAGE * GST * 4)   // 81920 B

__device__ __forceinline__ void gemm_f16_mainloop(
    uint32_t* sm, const uint32_t* __restrict__ A,
    const uint32_t* __restrict__ B, float acc[4][8][4])
{
    const int tid = threadIdx.x;
    const int wid = tid >> 5, lane = tid & 31;
    const int warp_m = wid & 1, warp_n = wid >> 1;
    const int g = lane >> 2, t = lane & 3;

    #pragma unroll
    for (int mi = 0; mi < 4; mi++)
        #pragma unroll
        for (int ni = 0; ni < 8; ni++)
            #pragma unroll
            for (int r = 0; r < 4; r++) acc[mi][ni][r] = 0.f;

    const uint32_t* Ar = A + (size_t)tid * (CC/2);
    const uint32_t* Br = B + (size_t)tid * (CC/2);
    const uint32_t smaddr = (uint32_t)__cvta_generic_to_shared(sm);
    const uint32_t abase = smaddr + (uint32_t)(tid * GP) * 4;
    const uint32_t bbase = smaddr + (uint32_t)(GSTA + tid * GP) * 4;

    // prologue: stages 0..2
    #pragma unroll
    for (int s = 0; s < NSTAGE - 1; s++) {
        #pragma unroll
        for (int u = 0; u < 4; u++)
            cp_async16(abase + s * (GST * 4) + u * 16, Ar + s * 16 + u * 4);
        #pragma unroll
        for (int u = 0; u < 4; u++)
            cp_async16(bbase + s * (GST * 4) + u * 16, Br + s * 16 + u * 4);
        cp_commit();
    }

    for (int c = 0; c < CC / 32; c++) {
        cp_wait2();            // stage c landed (per-thread)
        __syncthreads();       // all threads' copies visible

        uint32_t* As = sm + (c & 3) * GST;
        uint32_t* Bs = As + GSTA;
        #pragma unroll
        for (int ks = 0; ks < 2; ks++) {
            const int k8 = ks * 8;
            uint32_t af[4][4];
            #pragma unroll
            for (int mi = 0; mi < 4; mi++) {
                int mb = warp_m * 64 + mi * 16;
                af[mi][0] = As[(mb + g) * GP + k8 + t];
                af[mi][1] = As[(mb + g + 8) * GP + k8 + t];
                af[mi][2] = As[(mb + g) * GP + k8 + t + 4];
                af[mi][3] = As[(mb + g + 8) * GP + k8 + t + 4];
            }
            uint32_t bf[8][2];
            #pragma unroll
            for (int ni = 0; ni < 8; ni++) {
                int nb = warp_n * 64 + ni * 8;
                bf[ni][0] = Bs[(nb + g) * GP + k8 + t];
                bf[ni][1] = Bs[(nb + g) * GP + k8 + t + 4];
            }
            #pragma unroll
            for (int mi = 0; mi < 4; mi++)
                #pragma unroll
                for (int ni = 0; ni < 8; ni++)
                    mma_f16_16x8x16(acc[mi][ni], af[mi], bf[ni]);
        }

        // issue stage c+3 (buffer (c+3)&3 freed by the barrier above)
        if (c + NSTAGE - 1 < CC / 32) {
            const int cn = c + NSTAGE - 1;
            const uint32_t soff = (uint32_t)((cn & 3) * (GST * 4));
            #pragma unroll
            for (int u = 0; u < 4; u++)
                cp_async16(abase + soff + u * 16, Ar + cn * 16 + u * 4);
            #pragma unroll
            for (int u = 0; u < 4; u++)
                cp_async16(bbase + soff + u * 16, Br + cn * 16 + u * 4);
        }
        cp_commit();           // unconditional: keeps group counting exact at tail
    }
}

// ---------------------------------------------------------------------------
// Kernel 1: QKV projection. q,k -> [bh][t][d] fp16; v -> V^T [bh][d][t] fp16.
// grid (24, 32), block 128
// ---------------------------------------------------------------------------
__global__ __launch_bounds__(128, 2) void qkv_mma_kernel()
{
    extern __shared__ uint32_t smu[];
    const int bx = blockIdx.x;   // 0..23
    const int by = blockIdx.y;   // 0..31
    const int tid = threadIdx.x;
    const int wid = tid >> 5, lane = tid & 31;
    const int warp_m = wid & 1, warp_n = wid >> 1;
    const int g = lane >> 2, t = lane & 3;

    float acc[4][8][4];
    gemm_f16_mainloop(smu, g_xh + (size_t)(by * 128) * (CC/2),
                      g_wqh + (size_t)(bx * 128) * (CC/2), acc);

    const int g3 = bx >> 3;   // 0=q 1=k 2=v
    if (g3 < 2) {
        uint32_t* dstbase = (g3 == 0) ? g_q : g_k;
        #pragma unroll
        for (int mi = 0; mi < 4; mi++) {
            #pragma unroll
            for (int rr = 0; rr < 2; rr++) {
                int m = by * 128 + warp_m * 64 + mi * 16 + g + rr * 8;
                int b = m >> 11, tloc = m & (TT - 1);
                #pragma unroll
                for (int ni = 0; ni < 8; ni++) {
                    int n = bx * 128 + warp_n * 64 + ni * 8 + 2 * t;
                    int rem = n & 1023;
                    int h = rem >> 6, d = rem & 63;   // d even
                    dstbase[(((size_t)(b * HH + h)) * TT + tloc) * (DD/2) + (d >> 1)] =
                        pack_half2(acc[mi][ni][rr * 2], acc[mi][ni][rr * 2 + 1]);
                }
            }
        }
    } else {
        // V: write transposed fp16 scalars into g_vt [bh][d][t]
        unsigned short* vt = (unsigned short*)g_vt;
        #pragma unroll
        for (int mi = 0; mi < 4; mi++) {
            #pragma unroll
            for (int rr = 0; rr < 2; rr++) {
                int m = by * 128 + warp_m * 64 + mi * 16 + g + rr * 8;
                int b = m >> 11, tloc = m & (TT - 1);
                #pragma unroll
                for (int ni = 0; ni < 8; ni++) {
                    int n = bx * 128 + warp_n * 64 + ni * 8 + 2 * t;
                    int rem = n & 1023;
                    int h = rem >> 6, d = rem & 63;
                    size_t base = ((size_t)(b * HH + h) * DD + d) * TT + tloc;
                    vt[base]      = __half_as_ushort(__float2half_rn(acc[mi][ni][rr * 2]));
                    vt[base + TT] = __half_as_ushort(__float2half_rn(acc[mi][ni][rr * 2 + 1]));
                }
            }
        }
    }
}

// ---------------------------------------------------------------------------
// Kernel 3: out = y @ w_proj + b_proj (fp32 out)
// grid (8, 32), block 128
// ---------------------------------------------------------------------------
__global__ __launch_bounds__(128, 2) void proj_mma_kernel(
    const float* __restrict__ bias, float* __restrict__ out)
{
    extern __shared__ uint32_t smu[];
    const int bx = blockIdx.x;
    const int by = blockIdx.y;
    const int tid = threadIdx.x;
    const int wid = tid >> 5, lane = tid & 31;
    const int warp_m = wid & 1, warp_n = wid >> 1;
    const int g = lane >> 2, t = lane & 3;

    float acc[4][8][4];
    gemm_f16_mainloop(smu, g_yh + (size_t)(by * 128) * (CC/2),
                      g_wph + (size_t)(bx * 128) * (CC/2), acc);

    #pragma unroll
    for (int mi = 0; mi < 4; mi++) {
        #pragma unroll
        for (int rr = 0; rr < 2; rr++) {
            int m = by * 128 + warp_m * 64 + mi * 16 + g + rr * 8;
            #pragma unroll
            for (int ni = 0; ni < 8; ni++) {
                int n = bx * 128 + warp_n * 64 + ni * 8 + 2 * t;
                float2 v2;
                v2.x = acc[mi][ni][rr * 2]     + bias[n];
                v2.y = acc[mi][ni][rr * 2 + 1] + bias[n + 1];
                *(float2*)&out[(size_t)m * CC + n] = v2;
            }
        }
    }
}

// ===========================================================================
// Flash attention, fp16 mma (unchanged from R11 passing version).
// ===========================================================================
#define ATP 36
#define AST (64*ATP*2)                    // stage u32 = 4608
#define FA_SMEM_BYTES (2 * AST * 4)       // 36864

__global__ __launch_bounds__(256, 2) void flash_attn_f16_kernel()
{
    extern __shared__ uint32_t smu[];

    const int qi = (int)gridDim.x - 1 - (int)blockIdx.x;   // heavy CTAs first
    const int bh = blockIdx.y;
    const int b = bh >> 4, h = bh & 15;
    const int tid = threadIdx.x;
    const int wid = tid >> 5, lane = tid & 31;
    const int g = lane >> 2, t = lane & 3;
    const int wbase = wid * 16;

    // ---- Q fragments straight from gmem ----
    const uint32_t* q0 = g_q + ((size_t)bh * TT + qi * 128 + wbase + g) * (DD/2);
    const uint32_t* q1 = q0 + 8 * (DD/2);
    uint32_t qf[4][4];
    #pragma unroll
    for (int ks = 0; ks < 4; ks++) {
        qf[ks][0] = q0[ks * 8 + t];
        qf[ks][1] = q1[ks * 8 + t];
        qf[ks][2] = q0[ks * 8 + t + 4];
        qf[ks][3] = q1[ks * 8 + t + 4];
    }

    const int nkt = 2 * qi + 2;
    const int krow = tid >> 2, u = tid & 3;     // K: key row / V: d row

    // ---- prologue: FULL tile 0 -> stage 0 (two uint4 per thread) ----
    uint4 rk[2], rv[2];
    {
        const uint32_t* kp = g_k + ((size_t)bh * TT + krow) * (DD/2);
        const uint32_t* vp = g_vt + ((size_t)bh * DD + krow) * (TT/2);
        rk[0] = *(const uint4*)(kp + u * 4);
        rk[1] = *(const uint4*)(kp + u * 4 + 16);
        rv[0] = *(const uint4*)(vp + u * 4);
        rv[1] = *(const uint4*)(vp + u * 4 + 16);
        uint32_t* Kh = smu;
        uint32_t* Vh = smu + 64 * ATP;
        *(uint4*)&Kh[krow * ATP + u * 4]      = rk[0];
        *(uint4*)&Kh[krow * ATP + u * 4 + 16] = rk[1];
        *(uint4*)&Vh[krow * ATP + u * 4]      = rv[0];
        *(uint4*)&Vh[krow * ATP + u * 4 + 16] = rv[1];
    }
    __syncthreads();

    float of[8][4];
    #pragma unroll
    for (int nf = 0; nf < 8; nf++)
        #pragma unroll
        for (int r = 0; r < 4; r++) of[nf][r] = 0.f;
    float m0 = -1e30f, m1 = -1e30f, l0 = 0.f, l1 = 0.f;

    const int qrow0 = qi * 128 + wbase + g;
    const int qrow1 = qrow0 + 8;

    for (int kt = 0; kt < nkt; kt++) {
        uint32_t* Ksc = smu + (kt & 1) * AST;
        uint32_t* Vsc = Ksc + 64 * ATP;
        const bool more = (kt + 1 < nkt);

        if (more) {
            const uint32_t* kp = g_k + ((size_t)bh * TT + (kt + 1) * 64 + krow) * (DD/2);
            const uint32_t* vp = g_vt + ((size_t)bh * DD + krow) * (TT/2) + (kt + 1) * 32;
            rk[0] = *(const uint4*)(kp + u * 4);
            rk[1] = *(const uint4*)(kp + u * 4 + 16);
            rv[0] = *(const uint4*)(vp + u * 4);
            rv[1] = *(const uint4*)(vp + u * 4 + 16);
        }

        // ---- S = Q @ K^T ----
        float sf[8][4];
        #pragma unroll
        for (int nf = 0; nf < 8; nf++)
            #pragma unroll
            for (int r = 0; r < 4; r++) sf[nf][r] = 0.f;

        #pragma unroll
        for (int ks = 0; ks < 4; ks++) {
            #pragma unroll
            for (int nf = 0; nf < 8; nf++) {
                uint32_t bfr[2];
                bfr[0] = Ksc[(nf * 8 + g) * ATP + ks * 8 + t];
                bfr[1] = Ksc[(nf * 8 + g) * ATP + ks * 8 + t + 4];
                mma_f16_16x8x16(sf[nf], qf[ks], bfr);
            }
        }

        // ---- scale + causal mask ----
        const bool need_mask = (kt >= 2 * qi);
        #pragma unroll
        for (int nf = 0; nf < 8; nf++) {
            int kc0 = kt * 64 + nf * 8 + 2 * t;
            int kc1 = kc0 + 1;
            if (need_mask) {
                sf[nf][0] = (kc0 <= qrow0) ? sf[nf][0] * SCALE : -1e30f;
                sf[nf][1] = (kc1 <= qrow0) ? sf[nf][1] * SCALE : -1e30f;
                sf[nf][2] = (kc0 <= qrow1) ? sf[nf][2] * SCALE : -1e30f;
                sf[nf][3] = (kc1 <= qrow1) ? sf[nf][3] * SCALE : -1e30f;
            } else {
                sf[nf][0] *= SCALE; sf[nf][1] *= SCALE;
                sf[nf][2] *= SCALE; sf[nf][3] *= SCALE;
            }
        }

        // ---- online softmax ----
        float mx0 = -1e30f, mx1 = -1e30f;
        #pragma unroll
        for (int nf = 0; nf < 8; nf++) {
            mx0 = fmaxf(mx0, fmaxf(sf[nf][0], sf[nf][1]));
            mx1 = fmaxf(mx1, fmaxf(sf[nf][2], sf[nf][3]));
        }
        #pragma unroll
        for (int off = 1; off < 4; off <<= 1) {
            mx0 = fmaxf(mx0, __shfl_xor_sync(0xffffffffu, mx0, off));
            mx1 = fmaxf(mx1, __shfl_xor_sync(0xffffffffu, mx1, off));
        }
        float mn0 = fmaxf(m0, mx0), mn1 = fmaxf(m1, mx1);
        float a0 = __expf(m0 - mn0), a1 = __expf(m1 - mn1);
        m0 = mn0; m1 = mn1;

        float s0 = 0.f, s1 = 0.f;
        #pragma unroll
        for (int nf = 0; nf < 8; nf++) {
            sf[nf][0] = __expf(sf[nf][0] - mn0);
            sf[nf][1] = __expf(sf[nf][1] - mn0);
            sf[nf][2] = __expf(sf[nf][2] - mn1);
            sf[nf][3] = __expf(sf[nf][3] - mn1);
            s0 += sf[nf][0] + sf[nf][1];
            s1 += sf[nf][2] + sf[nf][3];
        }
        #pragma unroll
        for (int off = 1; off < 4; off <<= 1) {
            s0 += __shfl_xor_sync(0xffffffffu, s0, off);
            s1 += __shfl_xor_sync(0xffffffffu, s1, off);
        }
        l0 = l0 * a0 + s0;
        l1 = l1 * a1 + s1;

        // ---- P -> fp16 a-frags (registers only) ----
        uint32_t pf[4][4];
        #pragma unroll
        for (int ks = 0; ks < 4; ks++) {
            pf[ks][0] = pack_half2(sf[2*ks][0],     sf[2*ks][1]);
            pf[ks][1] = pack_half2(sf[2*ks][2],     sf[2*ks][3]);
            pf[ks][2] = pack_half2(sf[2*ks + 1][0], sf[2*ks + 1][1]);
            pf[ks][3] = pack_half2(sf[2*ks + 1][2], sf[2*ks + 1][3]);
        }

        // ---- store next K/V into the other stage (full tile) ----
        if (more) {
            uint32_t* Ksn = smu + ((kt + 1) & 1) * AST;
            uint32_t* Vsn = Ksn + 64 * ATP;
            *(uint4*)&Ksn[krow * ATP + u * 4]      = rk[0];
            *(uint4*)&Ksn[krow * ATP + u * 4 + 16] = rk[1];
            *(uint4*)&Vsn[krow * ATP + u * 4]      = rv[0];
            *(uint4*)&Vsn[krow * ATP + u * 4 + 16] = rv[1];
        }

        // ---- rescale O, then O += P @ V ----
        #pragma unroll
        for (int nf = 0; nf < 8; nf++) {
            of[nf][0] *= a0; of[nf][1] *= a0;
            of[nf][2] *= a1; of[nf][3] *= a1;
        }
        #pragma unroll
        for (int ks = 0; ks < 4; ks++) {
            #pragma unroll
            for (int nf = 0; nf < 8; nf++) {
                uint32_t bfr[2];
                bfr[0] = Vsc[(nf * 8 + g) * ATP + ks * 8 + t];
                bfr[1] = Vsc[(nf * 8 + g) * ATP + ks * 8 + t + 4];
                mma_f16_16x8x16(of[nf], pf[ks], bfr);
            }
        }
        __syncthreads();
    }

    // ---- epilogue: normalize -> fp16 -> g_yh ----
    float inv0 = 1.f / l0, inv1 = 1.f / l1;
    const int t0 = qi * 128 + wbase + g;
    const int t1 = t0 + 8;
    uint32_t* y0 = g_yh + ((size_t)b * TT + t0) * (CC/2) + h * (DD/2);
    uint32_t* y1 = g_yh + ((size_t)b * TT + t1) * (CC/2) + h * (DD/2);
    #pragma unroll
    for (int nf = 0; nf < 8; nf++) {
        int d2 = nf * 4 + t;
        y0[d2] = pack_half2(of[nf][0] * inv0, of[nf][1] * inv0);
        y1[d2] = pack_half2(of[nf][2] * inv1, of[nf][3] * inv1);
    }
}

// ---------------------------------------------------------------------------
extern "C" void kernel_launch(void* const* d_in, const int* in_sizes, int n_in,
                              void* d_out, int out_size)
{
    const float* x      = (const float*)d_in[0];
    const float* w_qkv  = (const float*)d_in[1];
    const float* w_proj = (const float*)d_in[2];
    const float* b_proj = (const float*)d_in[3];
    float* out = (float*)d_out;

    static bool attr_set = false;
    if (!attr_set) {
        cudaFuncSetAttribute(flash_attn_f16_kernel,
                             cudaFuncAttributeMaxDynamicSharedMemorySize,
                             FA_SMEM_BYTES);
        cudaFuncSetAttribute(qkv_mma_kernel,
                             cudaFuncAttributeMaxDynamicSharedMemorySize,
                             GEMM_SMEM_BYTES);
        cudaFuncSetAttribute(proj_mma_kernel,
                             cudaFuncAttributeMaxDynamicSharedMemorySize,
                             GEMM_SMEM_BYTES);
        attr_set = true;
    }

    uint32_t* xh;  cudaGetSymbolAddress((void**)&xh,  g_xh);
    uint32_t* wqh; cudaGetSymbolAddress((void**)&wqh, g_wqh);
    uint32_t* wph; cudaGetSymbolAddress((void**)&wph, g_wph);

    // 0) input conversion: x -> fp16 row-major; weights -> fp16 transposed
    conv_f16_kernel<<<1184, 256>>>((const float4*)x, (uint2*)xh, MROWS * CC / 4);
    {
        dim3 grid(3 * CC / 32, CC / 32);   // (96, 32)
        trans_f16_kernel<<<grid, 256>>>(w_qkv, wqh, 3 * CC, CC);
    }
    {
        dim3 grid(CC / 32, CC / 32);       // (32, 32)
        trans_f16_kernel<<<grid, 256>>>(w_proj, wph, CC, CC);
    }

    // 1) QKV projection + scatter (q,k row-major; v transposed)
    {
        dim3 grid(3 * CC / 128, MROWS / 128);   // (24, 32)
        qkv_mma_kernel<<<grid, 128, GEMM_SMEM_BYTES>>>();
    }
    // 2) flash attention
    {
        dim3 grid(TT / 128, BB * HH);           // (16, 32)
        flash_attn_f16_kernel<<<grid, 256, FA_SMEM_BYTES>>>();
    }
    // 3) output projection + bias
    {
        dim3 grid(CC / 128, MROWS / 128);       // (8, 32)
        proj_mma_kernel<<<grid, 128, GEMM_SMEM_BYTES>>>(b_proj, out);
    }
}

// round 13
// speedup vs baseline: 6.7575x; 1.2905x over previous
#include <cuda_runtime.h>
#include <cuda_fp16.h>
#include <cstdint>

// Problem constants
#define BB   2
#define TT   2048
#define CC   1024
#define HH   16
#define DD   64
#define MROWS (BB*TT)          // 4096
#define SCALE 0.125f           // 1/sqrt(64)

// Scratch (device globals). fp16 data stored as packed u32 (half2 pairs).
__device__ uint32_t g_xh [MROWS*CC/2];     // x fp16 [M][C]
__device__ uint32_t g_wqh[3*CC*CC/2];      // w_qkv^T fp16 [3C][C]  ([n][k])
__device__ uint32_t g_wph[CC*CC/2];        // w_proj^T fp16 [C][C]
__device__ uint32_t g_q  [BB*HH*TT*DD/2];  // [bh][t][d] fp16
__device__ uint32_t g_k  [BB*HH*TT*DD/2];  // [bh][t][d] fp16
__device__ uint32_t g_vt [BB*HH*DD*TT/2];  // V^T: [bh][d][t] fp16
__device__ uint32_t g_yh [MROWS*CC/2];     // attention out fp16 [M][C]

// ===========================================================================
// helpers
// ===========================================================================
__device__ __forceinline__ uint32_t pack_half2(float lo, float hi) {
    uint32_t u;
    asm("cvt.rn.f16x2.f32 %0, %1, %2;" : "=r"(u) : "f"(hi), "f"(lo));
    return u;
}

__device__ __forceinline__ void mma_f16_16x8x16(float* c, const uint32_t* a,
                                                const uint32_t* b) {
    asm volatile(
        "mma.sync.aligned.m16n8k16.row.col.f32.f16.f16.f32 "
        "{%0,%1,%2,%3}, {%4,%5,%6,%7}, {%8,%9}, {%0,%1,%2,%3};\n"
        : "+f"(c[0]), "+f"(c[1]), "+f"(c[2]), "+f"(c[3])
        : "r"(a[0]), "r"(a[1]), "r"(a[2]), "r"(a[3]),
          "r"(b[0]), "r"(b[1]));
}

__device__ __forceinline__ void ldsm_x4(uint32_t* r, uint32_t saddr) {
    asm volatile("ldmatrix.sync.aligned.m8n8.x4.shared.b16 {%0,%1,%2,%3}, [%4];"
        : "=r"(r[0]), "=r"(r[1]), "=r"(r[2]), "=r"(r[3]) : "r"(saddr));
}

__device__ __forceinline__ void cp_async16(uint32_t dst, const void* src) {
    asm volatile("cp.async.cg.shared.global [%0], [%1], 16;"
                 :: "r"(dst), "l"(src));
}
__device__ __forceinline__ void cp_commit() {
    asm volatile("cp.async.commit_group;" ::: "memory");
}
__device__ __forceinline__ void cp_wait2() {
    asm volatile("cp.async.wait_group 2;" ::: "memory");
}

// ---------------------------------------------------------------------------
// Kernel 0a: fp32 -> fp16 bulk convert
// ---------------------------------------------------------------------------
__global__ __launch_bounds__(256) void conv_f16_kernel(
    const float4* __restrict__ in, uint2* __restrict__ out, int n4)
{
    int i = blockIdx.x * blockDim.x + threadIdx.x;
    int stride = gridDim.x * blockDim.x;
    for (; i < n4; i += stride) {
        float4 v = in[i];
        uint2 o;
        o.x = pack_half2(v.x, v.y);
        o.y = pack_half2(v.z, v.w);
        out[i] = o;
    }
}

// ---------------------------------------------------------------------------
// Kernel 0b: fp32 [K][N] -> fp16 [N][K] transpose (weights)
// ---------------------------------------------------------------------------
__global__ __launch_bounds__(256) void trans_f16_kernel(
    const float* __restrict__ in, uint32_t* __restrict__ out, int N, int K)
{
    __shared__ float ts[32][33];
    const int k0 = blockIdx.y * 32, n0 = blockIdx.x * 32;
    const int tx = threadIdx.x & 31, ty = threadIdx.x >> 5;
    #pragma unroll
    for (int j = 0; j < 4; j++)
        ts[ty + 8*j][tx] = in[(size_t)(k0 + ty + 8*j) * N + n0 + tx];
    __syncthreads();
    const int n = threadIdx.x >> 3, c = threadIdx.x & 7;
    out[(size_t)(n0 + n) * (K >> 1) + (k0 >> 1) + c] =
        pack_half2(ts[2*c][n], ts[2*c + 1][n]);
    out[(size_t)(n0 + n) * (K >> 1) + (k0 >> 1) + c + 8] =
        pack_half2(ts[2*c + 16][n], ts[2*c + 17][n]);
}

// ===========================================================================
// fp16 GEMM mainloop, cp.async 4-stage + ldmatrix.
// CTA 128x128, 256 threads (8 warps: 4 along M x 2 along N), warp tile 32x64.
// K chunk 32 fp16 (16 u32). Stage: A [128][GP] + B [128][GP], pitch 20 u32.
// ===========================================================================
#define GP 20
#define GSTA (128*GP)                    // A part u32 per stage
#define GST (2*GSTA)                     // stage u32 = 5120 (20480 B)
#define NSTAGE 4
#define GEMM_SMEM_BYTES (NSTAGE * GST * 4)   // 81920 B

__device__ __forceinline__ void gemm_f16_mainloop(
    uint32_t* sm, const uint32_t* __restrict__ A,
    const uint32_t* __restrict__ B, float acc[2][8][4])
{
    const int tid = threadIdx.x;
    const int wid = tid >> 5, lane = tid & 31;
    const int warp_m = wid & 3;          // 4 warps along M (32 rows each)
    const int warp_n = wid >> 2;         // 2 warps along N (64 cols each)

    #pragma unroll
    for (int mi = 0; mi < 2; mi++)
        #pragma unroll
        for (int ni = 0; ni < 8; ni++)
            #pragma unroll
            for (int r = 0; r < 4; r++) acc[mi][ni][r] = 0.f;

    // cp.async mapping: 512 16B-chunks each for A and B per stage.
    // idx = u*256 + tid (u=0,1): row = idx>>2, seg = idx&3 (64B-coalesced groups)
    const int r0 = tid >> 2, s0 = tid & 3;             // u=0
    const int r1 = (256 + tid) >> 2, s1 = tid & 3;     // u=1 (row + 64)
    const uint32_t smaddr = (uint32_t)__cvta_generic_to_shared(sm);

    // prologue: stages 0..2
    #pragma unroll
    for (int s = 0; s < NSTAGE - 1; s++) {
        const uint32_t so = (uint32_t)(s * GST * 4);
        cp_async16(smaddr + so + (uint32_t)(r0 * GP + s0 * 4) * 4,
                   A + (size_t)r0 * (CC/2) + s * 16 + s0 * 4);
        cp_async16(smaddr + so + (uint32_t)(r1 * GP + s1 * 4) * 4,
                   A + (size_t)r1 * (CC/2) + s * 16 + s1 * 4);
        cp_async16(smaddr + so + (uint32_t)(GSTA + r0 * GP + s0 * 4) * 4,
                   B + (size_t)r0 * (CC/2) + s * 16 + s0 * 4);
        cp_async16(smaddr + so + (uint32_t)(GSTA + r1 * GP + s1 * 4) * 4,
                   B + (size_t)r1 * (CC/2) + s * 16 + s1 * 4);
        cp_commit();
    }

    // ldmatrix lane addressing (lane-invariant parts)
    const int lq = lane >> 3, lr = lane & 7;
    const int a_row  = warp_m * 32 + lr + 8 * (lq & 1);   // + mi*16
    const int a_col  = 4 * (lq >> 1);                      // + ks*8
    const int b_row  = warp_n * 64 + lr + 8 * (lq >> 1);   // + nfp*16
    const int b_col  = 4 * (lq & 1);                       // + ks*8

    for (int c = 0; c < CC / 32; c++) {
        cp_wait2();
        __syncthreads();

        const uint32_t sa = smaddr + (uint32_t)((c & 3) * GST) * 4;
        const uint32_t sb = sa + (uint32_t)GSTA * 4;

        uint32_t af[2][2][4];   // [mi][ks][4]
        #pragma unroll
        for (int mi = 0; mi < 2; mi++)
            #pragma unroll
            for (int ks = 0; ks < 2; ks++)
                ldsm_x4(af[mi][ks],
                        sa + (uint32_t)((a_row + mi * 16) * GP + ks * 8 + a_col) * 4);

        uint32_t bf[4][2][4];   // [nfp][ks][4] -> {b0,b1} even nf, {b0,b1} odd nf
        #pragma unroll
        for (int nfp = 0; nfp < 4; nfp++)
            #pragma unroll
            for (int ks = 0; ks < 2; ks++)
                ldsm_x4(bf[nfp][ks],
                        sb + (uint32_t)((b_row + nfp * 16) * GP + ks * 8 + b_col) * 4);

        #pragma unroll
        for (int mi = 0; mi < 2; mi++)
            #pragma unroll
            for (int nfp = 0; nfp < 4; nfp++)
                #pragma unroll
                for (int ks = 0; ks < 2; ks++) {
                    mma_f16_16x8x16(acc[mi][2 * nfp],     af[mi][ks], &bf[nfp][ks][0]);
                    mma_f16_16x8x16(acc[mi][2 * nfp + 1], af[mi][ks], &bf[nfp][ks][2]);
                }

        // issue stage c+3
        if (c + NSTAGE - 1 < CC / 32) {
            const int cn = c + NSTAGE - 1;
            const uint32_t so = (uint32_t)((cn & 3) * GST * 4);
            cp_async16(smaddr + so + (uint32_t)(r0 * GP + s0 * 4) * 4,
                       A + (size_t)r0 * (CC/2) + cn * 16 + s0 * 4);
            cp_async16(smaddr + so + (uint32_t)(r1 * GP + s1 * 4) * 4,
                       A + (size_t)r1 * (CC/2) + cn * 16 + s1 * 4);
            cp_async16(smaddr + so + (uint32_t)(GSTA + r0 * GP + s0 * 4) * 4,
                       B + (size_t)r0 * (CC/2) + cn * 16 + s0 * 4);
            cp_async16(smaddr + so + (uint32_t)(GSTA + r1 * GP + s1 * 4) * 4,
                       B + (size_t)r1 * (CC/2) + cn * 16 + s1 * 4);
        }
        cp_commit();
    }
}

// ---------------------------------------------------------------------------
// Kernel 1: QKV projection. q,k -> [bh][t][d] fp16; v -> V^T [bh][d][t] fp16.
// grid (24, 32), block 256
// ---------------------------------------------------------------------------
__global__ __launch_bounds__(256, 2) void qkv_mma_kernel()
{
    extern __shared__ uint32_t smu[];
    const int bx = blockIdx.x;   // 0..23
    const int by = blockIdx.y;   // 0..31
    const int tid = threadIdx.x;
    const int wid = tid >> 5, lane = tid & 31;
    const int warp_m = wid & 3, warp_n = wid >> 2;
    const int g = lane >> 2, t = lane & 3;

    float acc[2][8][4];
    gemm_f16_mainloop(smu, g_xh + (size_t)(by * 128) * (CC/2),
                      g_wqh + (size_t)(bx * 128) * (CC/2), acc);

    const int g3 = bx >> 3;   // 0=q 1=k 2=v
    if (g3 < 2) {
        uint32_t* dstbase = (g3 == 0) ? g_q : g_k;
        #pragma unroll
        for (int mi = 0; mi < 2; mi++) {
            #pragma unroll
            for (int rr = 0; rr < 2; rr++) {
                int m = by * 128 + warp_m * 32 + mi * 16 + g + rr * 8;
                int b = m >> 11, tloc = m & (TT - 1);
                #pragma unroll
                for (int ni = 0; ni < 8; ni++) {
                    int n = bx * 128 + warp_n * 64 + ni * 8 + 2 * t;
                    int rem = n & 1023;
                    int h = rem >> 6, d = rem & 63;   // d even
                    dstbase[(((size_t)(b * HH + h)) * TT + tloc) * (DD/2) + (d >> 1)] =
                        pack_half2(acc[mi][ni][rr * 2], acc[mi][ni][rr * 2 + 1]);
                }
            }
        }
    } else {
        // V: write transposed fp16 scalars into g_vt [bh][d][t]
        unsigned short* vt = (unsigned short*)g_vt;
        #pragma unroll
        for (int mi = 0; mi < 2; mi++) {
            #pragma unroll
            for (int rr = 0; rr < 2; rr++) {
                int m = by * 128 + warp_m * 32 + mi * 16 + g + rr * 8;
                int b = m >> 11, tloc = m & (TT - 1);
                #pragma unroll
                for (int ni = 0; ni < 8; ni++) {
                    int n = bx * 128 + warp_n * 64 + ni * 8 + 2 * t;
                    int rem = n & 1023;
                    int h = rem >> 6, d = rem & 63;
                    size_t base = ((size_t)(b * HH + h) * DD + d) * TT + tloc;
                    vt[base]      = __half_as_ushort(__float2half_rn(acc[mi][ni][rr * 2]));
                    vt[base + TT] = __half_as_ushort(__float2half_rn(acc[mi][ni][rr * 2 + 1]));
                }
            }
        }
    }
}

// ---------------------------------------------------------------------------
// Kernel 3: out = y @ w_proj + b_proj (fp32 out)
// grid (8, 32), block 256
// ---------------------------------------------------------------------------
__global__ __launch_bounds__(256, 2) void proj_mma_kernel(
    const float* __restrict__ bias, float* __restrict__ out)
{
    extern __shared__ uint32_t smu[];
    const int bx = blockIdx.x;
    const int by = blockIdx.y;
    const int tid = threadIdx.x;
    const int wid = tid >> 5, lane = tid & 31;
    const int warp_m = wid & 3, warp_n = wid >> 2;
    const int g = lane >> 2, t = lane & 3;

    float acc[2][8][4];
    gemm_f16_mainloop(smu, g_yh + (size_t)(by * 128) * (CC/2),
                      g_wph + (size_t)(bx * 128) * (CC/2), acc);

    #pragma unroll
    for (int mi = 0; mi < 2; mi++) {
        #pragma unroll
        for (int rr = 0; rr < 2; rr++) {
            int m = by * 128 + warp_m * 32 + mi * 16 + g + rr * 8;
            #pragma unroll
            for (int ni = 0; ni < 8; ni++) {
                int n = bx * 128 + warp_n * 64 + ni * 8 + 2 * t;
                float2 v2;
                v2.x = acc[mi][ni][rr * 2]     + bias[n];
                v2.y = acc[mi][ni][rr * 2 + 1] + bias[n + 1];
                *(float2*)&out[(size_t)m * CC + n] = v2;
            }
        }
    }
}

// ===========================================================================
// Flash attention, fp16 mma (unchanged from R12 passing version).
// ===========================================================================
#define ATP 36
#define AST (64*ATP*2)                    // stage u32 = 4608
#define FA_SMEM_BYTES (2 * AST * 4)       // 36864

__global__ __launch_bounds__(256, 2) void flash_attn_f16_kernel()
{
    extern __shared__ uint32_t smu[];

    const int qi = (int)gridDim.x - 1 - (int)blockIdx.x;   // heavy CTAs first
    const int bh = blockIdx.y;
    const int b = bh >> 4, h = bh & 15;
    const int tid = threadIdx.x;
    const int wid = tid >> 5, lane = tid & 31;
    const int g = lane >> 2, t = lane & 3;
    const int wbase = wid * 16;

    // ---- Q fragments straight from gmem ----
    const uint32_t* q0 = g_q + ((size_t)bh * TT + qi * 128 + wbase + g) * (DD/2);
    const uint32_t* q1 = q0 + 8 * (DD/2);
    uint32_t qf[4][4];
    #pragma unroll
    for (int ks = 0; ks < 4; ks++) {
        qf[ks][0] = q0[ks * 8 + t];
        qf[ks][1] = q1[ks * 8 + t];
        qf[ks][2] = q0[ks * 8 + t + 4];
        qf[ks][3] = q1[ks * 8 + t + 4];
    }

    const int nkt = 2 * qi + 2;
    const int krow = tid >> 2, u = tid & 3;     // K: key row / V: d row

    // ---- prologue: FULL tile 0 -> stage 0 (two uint4 per thread) ----
    uint4 rk[2], rv[2];
    {
        const uint32_t* kp = g_k + ((size_t)bh * TT + krow) * (DD/2);
        const uint32_t* vp = g_vt + ((size_t)bh * DD + krow) * (TT/2);
        rk[0] = *(const uint4*)(kp + u * 4);
        rk[1] = *(const uint4*)(kp + u * 4 + 16);
        rv[0] = *(const uint4*)(vp + u * 4);
        rv[1] = *(const uint4*)(vp + u * 4 + 16);
        uint32_t* Kh = smu;
        uint32_t* Vh = smu + 64 * ATP;
        *(uint4*)&Kh[krow * ATP + u * 4]      = rk[0];
        *(uint4*)&Kh[krow * ATP + u * 4 + 16] = rk[1];
        *(uint4*)&Vh[krow * ATP + u * 4]      = rv[0];
        *(uint4*)&Vh[krow * ATP + u * 4 + 16] = rv[1];
    }
    __syncthreads();

    float of[8][4];
    #pragma unroll
    for (int nf = 0; nf < 8; nf++)
        #pragma unroll
        for (int r = 0; r < 4; r++) of[nf][r] = 0.f;
    float m0 = -1e30f, m1 = -1e30f, l0 = 0.f, l1 = 0.f;

    const int qrow0 = qi * 128 + wbase + g;
    const int qrow1 = qrow0 + 8;

    for (int kt = 0; kt < nkt; kt++) {
        uint32_t* Ksc = smu + (kt & 1) * AST;
        uint32_t* Vsc = Ksc + 64 * ATP;
        const bool more = (kt + 1 < nkt);

        if (more) {
            const uint32_t* kp = g_k + ((size_t)bh * TT + (kt + 1) * 64 + krow) * (DD/2);
            const uint32_t* vp = g_vt + ((size_t)bh * DD + krow) * (TT/2) + (kt + 1) * 32;
            rk[0] = *(const uint4*)(kp + u * 4);
            rk[1] = *(const uint4*)(kp + u * 4 + 16);
            rv[0] = *(const uint4*)(vp + u * 4);
            rv[1] = *(const uint4*)(vp + u * 4 + 16);
        }

        // ---- S = Q @ K^T ----
        float sf[8][4];
        #pragma unroll
        for (int nf = 0; nf < 8; nf++)
            #pragma unroll
            for (int r = 0; r < 4; r++) sf[nf][r] = 0.f;

        #pragma unroll
        for (int ks = 0; ks < 4; ks++) {
            #pragma unroll
            for (int nf = 0; nf < 8; nf++) {
                uint32_t bfr[2];
                bfr[0] = Ksc[(nf * 8 + g) * ATP + ks * 8 + t];
                bfr[1] = Ksc[(nf * 8 + g) * ATP + ks * 8 + t + 4];
                mma_f16_16x8x16(sf[nf], qf[ks], bfr);
            }
        }

        // ---- scale + causal mask ----
        const bool need_mask = (kt >= 2 * qi);
        #pragma unroll
        for (int nf = 0; nf < 8; nf++) {
            int kc0 = kt * 64 + nf * 8 + 2 * t;
            int kc1 = kc0 + 1;
            if (need_mask) {
                sf[nf][0] = (kc0 <= qrow0) ? sf[nf][0] * SCALE : -1e30f;
                sf[nf][1] = (kc1 <= qrow0) ? sf[nf][1] * SCALE : -1e30f;
                sf[nf][2] = (kc0 <= qrow1) ? sf[nf][2] * SCALE : -1e30f;
                sf[nf][3] = (kc1 <= qrow1) ? sf[nf][3] * SCALE : -1e30f;
            } else {
                sf[nf][0] *= SCALE; sf[nf][1] *= SCALE;
                sf[nf][2] *= SCALE; sf[nf][3] *= SCALE;
            }
        }

        // ---- online softmax ----
        float mx0 = -1e30f, mx1 = -1e30f;
        #pragma unroll
        for (int nf = 0; nf < 8; nf++) {
            mx0 = fmaxf(mx0, fmaxf(sf[nf][0], sf[nf][1]));
            mx1 = fmaxf(mx1, fmaxf(sf[nf][2], sf[nf][3]));
        }
        #pragma unroll
        for (int off = 1; off < 4; off <<= 1) {
            mx0 = fmaxf(mx0, __shfl_xor_sync(0xffffffffu, mx0, off));
            mx1 = fmaxf(mx1, __shfl_xor_sync(0xffffffffu, mx1, off));
        }
        float mn0 = fmaxf(m0, mx0), mn1 = fmaxf(m1, mx1);
        float a0 = __expf(m0 - mn0), a1 = __expf(m1 - mn1);
        m0 = mn0; m1 = mn1;

        float s0 = 0.f, s1 = 0.f;
        #pragma unroll
        for (int nf = 0; nf < 8; nf++) {
            sf[nf][0] = __expf(sf[nf][0] - mn0);
            sf[nf][1] = __expf(sf[nf][1] - mn0);
            sf[nf][2] = __expf(sf[nf][2] - mn1);
            sf[nf][3] = __expf(sf[nf][3] - mn1);
            s0 += sf[nf][0] + sf[nf][1];
            s1 += sf[nf][2] + sf[nf][3];
        }
        #pragma unroll
        for (int off = 1; off < 4; off <<= 1) {
            s0 += __shfl_xor_sync(0xffffffffu, s0, off);
            s1 += __shfl_xor_sync(0xffffffffu, s1, off);
        }
        l0 = l0 * a0 + s0;
        l1 = l1 * a1 + s1;

        // ---- P -> fp16 a-frags (registers only) ----
        uint32_t pf[4][4];
        #pragma unroll
        for (int ks = 0; ks < 4; ks++) {
            pf[ks][0] = pack_half2(sf[2*ks][0],     sf[2*ks][1]);
            pf[ks][1] = pack_half2(sf[2*ks][2],     sf[2*ks][3]);
            pf[ks][2] = pack_half2(sf[2*ks + 1][0], sf[2*ks + 1][1]);
            pf[ks][3] = pack_half2(sf[2*ks + 1][2], sf[2*ks + 1][3]);
        }

        // ---- store next K/V into the other stage (full tile) ----
        if (more) {
            uint32_t* Ksn = smu + ((kt + 1) & 1) * AST;
            uint32_t* Vsn = Ksn + 64 * ATP;
            *(uint4*)&Ksn[krow * ATP + u * 4]      = rk[0];
            *(uint4*)&Ksn[krow * ATP + u * 4 + 16] = rk[1];
            *(uint4*)&Vsn[krow * ATP + u * 4]      = rv[0];
            *(uint4*)&Vsn[krow * ATP + u * 4 + 16] = rv[1];
        }

        // ---- rescale O, then O += P @ V ----
        #pragma unroll
        for (int nf = 0; nf < 8; nf++) {
            of[nf][0] *= a0; of[nf][1] *= a0;
            of[nf][2] *= a1; of[nf][3] *= a1;
        }
        #pragma unroll
        for (int ks = 0; ks < 4; ks++) {
            #pragma unroll
            for (int nf = 0; nf < 8; nf++) {
                uint32_t bfr[2];
                bfr[0] = Vsc[(nf * 8 + g) * ATP + ks * 8 + t];
                bfr[1] = Vsc[(nf * 8 + g) * ATP + ks * 8 + t + 4];
                mma_f16_16x8x16(of[nf], pf[ks], bfr);
            }
        }
        __syncthreads();
    }

    // ---- epilogue: normalize -> fp16 -> g_yh ----
    float inv0 = 1.f / l0, inv1 = 1.f / l1;
    const int t0 = qi * 128 + wbase + g;
    const int t1 = t0 + 8;
    uint32_t* y0 = g_yh + ((size_t)b * TT + t0) * (CC/2) + h * (DD/2);
    uint32_t* y1 = g_yh + ((size_t)b * TT + t1) * (CC/2) + h * (DD/2);
    #pragma unroll
    for (int nf = 0; nf < 8; nf++) {
        int d2 = nf * 4 + t;
        y0[d2] = pack_half2(of[nf][0] * inv0, of[nf][1] * inv0);
        y1[d2] = pack_half2(of[nf][2] * inv1, of[nf][3] * inv1);
    }
}

// ---------------------------------------------------------------------------
extern "C" void kernel_launch(void* const* d_in, const int* in_sizes, int n_in,
                              void* d_out, int out_size)
{
    const float* x      = (const float*)d_in[0];
    const float* w_qkv  = (const float*)d_in[1];
    const float* w_proj = (const float*)d_in[2];
    const float* b_proj = (const float*)d_in[3];
    float* out = (float*)d_out;

    static bool attr_set = false;
    if (!attr_set) {
        cudaFuncSetAttribute(flash_attn_f16_kernel,
                             cudaFuncAttributeMaxDynamicSharedMemorySize,
                             FA_SMEM_BYTES);
        cudaFuncSetAttribute(qkv_mma_kernel,
                             cudaFuncAttributeMaxDynamicSharedMemorySize,
                             GEMM_SMEM_BYTES);
        cudaFuncSetAttribute(proj_mma_kernel,
                             cudaFuncAttributeMaxDynamicSharedMemorySize,
                             GEMM_SMEM_BYTES);
        attr_set = true;
    }

    uint32_t* xh;  cudaGetSymbolAddress((void**)&xh,  g_xh);
    uint32_t* wqh; cudaGetSymbolAddress((void**)&wqh, g_wqh);
    uint32_t* wph; cudaGetSymbolAddress((void**)&wph, g_wph);

    // 0) input conversion: x -> fp16 row-major; weights -> fp16 transposed
    conv_f16_kernel<<<1184, 256>>>((const float4*)x, (uint2*)xh, MROWS * CC / 4);
    {
        dim3 grid(3 * CC / 32, CC / 32);   // (96, 32)
        trans_f16_kernel<<<grid, 256>>>(w_qkv, wqh, 3 * CC, CC);
    }
    {
        dim3 grid(CC / 32, CC / 32);       // (32, 32)
        trans_f16_kernel<<<grid, 256>>>(w_proj, wph, CC, CC);
    }

    // 1) QKV projection + scatter (q,k row-major; v transposed)
    {
        dim3 grid(3 * CC / 128, MROWS / 128);   // (24, 32)
        qkv_mma_kernel<<<grid, 256, GEMM_SMEM_BYTES>>>();
    }
    // 2) flash attention
    {
        dim3 grid(TT / 128, BB * HH);           // (16, 32)
        flash_attn_f16_kernel<<<grid, 256, FA_SMEM_BYTES>>>();
    }
    // 3) output projection + bias
    {
        dim3 grid(CC / 128, MROWS / 128);       // (8, 32)
        proj_mma_kernel<<<grid, 256, GEMM_SMEM_BYTES>>>(b_proj, out);
    }
}